// round 7
// baseline (speedup 1.0000x reference)
#include <cuda_runtime.h>
#include <cuda_bf16.h>
#include <cstdint>

// MMD loss: signed pairwise reduction over upper block-triangle of the
// 8192x8192 RBF kernel matrix. Gram via bf16 3-term split (hi*hi+hi*lo+lo*hi)
// on warp-level mma.sync, cp.async-pipelined staging, fused single-exp
// 5-kernel mixture epilogue.

#define NROWS 8192
#define NHALF 4096
#define DDIM  128

#define BM 128
#define BN 64                        // per-CTA column half
#define NB (NROWS / BM)              // 64
#define NPAIRS (NB * (NB + 1) / 2)   // 2080
#define NCTAS (NPAIRS * 2)           // 4160

#define SROW 272                     // padded row stride bytes (17 * 16B)
#define OFF_A_HI 0
#define OFF_A_LO (128 * SROW)
#define OFF_B_HI (2 * 128 * SROW)
#define OFF_B_LO (2 * 128 * SROW + 64 * SROW)
#define OFF_Q    (2 * 128 * SROW + 2 * 64 * SROW)   // 64 floats
#define OFF_RED  (OFF_Q + 256)                      // 256 floats
#define SMEM_DYN (OFF_RED + 1024)

// ---- device scratch ----
__device__ double g_S;
__device__ double g_colsum[DDIM];
__device__ float  g_rowsq[NROWS];
__device__ double g_acc;
__device__ float  g_c;
__device__ __align__(16) __nv_bfloat16 g_hi[NROWS * DDIM];
__device__ __align__(16) __nv_bfloat16 g_lo[NROWS * DDIM];

// ================= helpers =================
__device__ __forceinline__ uint32_t smem_u32(const void* p) {
    uint32_t a;
    asm("{ .reg .u64 t; cvta.to.shared.u64 t, %1; cvt.u32.u64 %0, t; }" : "=r"(a) : "l"(p));
    return a;
}
__device__ __forceinline__ float ex2f(float x) {
    float r; asm("ex2.approx.ftz.f32 %0, %1;" : "=f"(r) : "f"(x));
    return r;
}
__device__ __forceinline__ void cp_async16(uint32_t dst, const void* src) {
    asm volatile("cp.async.cg.shared.global [%0], [%1], 16;" :: "r"(dst), "l"(src) : "memory");
}
__device__ __forceinline__ void cp_commit() {
    asm volatile("cp.async.commit_group;" ::: "memory");
}
template <int N>
__device__ __forceinline__ void cp_wait() {
    asm volatile("cp.async.wait_group %0;" :: "n"(N) : "memory");
}

#define LDSM_X4(r0, r1, r2, r3, addr) \
    asm volatile("ldmatrix.sync.aligned.m8n8.x4.shared.b16 {%0,%1,%2,%3}, [%4];" \
        : "=r"(r0), "=r"(r1), "=r"(r2), "=r"(r3) : "r"(addr))

#define MMA_BF16(d, a, b) \
    asm volatile("mma.sync.aligned.m16n8k16.row.col.f32.bf16.bf16.f32 " \
        "{%0,%1,%2,%3}, {%4,%5,%6,%7}, {%8,%9}, {%0,%1,%2,%3};" \
        : "+f"((d)[0]), "+f"((d)[1]), "+f"((d)[2]), "+f"((d)[3]) \
        : "r"((a)[0]), "r"((a)[1]), "r"((a)[2]), "r"((a)[3]), "r"((b)[0]), "r"((b)[1]))

// f32x2 packed ops
typedef unsigned long long u64t;
__device__ __forceinline__ u64t pk(float a, float b) {
    u64t r; asm("mov.b64 %0, {%1, %2};" : "=l"(r) : "f"(a), "f"(b)); return r;
}
__device__ __forceinline__ void unpk(float& a, float& b, u64t v) {
    asm("mov.b64 {%0, %1}, %2;" : "=f"(a), "=f"(b) : "l"(v));
}
__device__ __forceinline__ u64t pk_fma(u64t a, u64t b, u64t c) {
    u64t r; asm("fma.rn.f32x2 %0, %1, %2, %3;" : "=l"(r) : "l"(a), "l"(b), "l"(c)); return r;
}
__device__ __forceinline__ u64t pk_mul(u64t a, u64t b) {
    u64t r; asm("mul.rn.f32x2 %0, %1, %2;" : "=l"(r) : "l"(a), "l"(b)); return r;
}
__device__ __forceinline__ u64t pk_add(u64t a, u64t b) {
    u64t r; asm("add.rn.f32x2 %0, %1, %2;" : "=l"(r) : "l"(a), "l"(b)); return r;
}

// ================= prep kernels =================
__global__ void k_init() {
    int t = threadIdx.x;
    if (t == 0) { g_S = 0.0; g_acc = 0.0; }
    if (t < DDIM) g_colsum[t] = 0.0;
}

// merged: rowsq + bf16 hi/lo split + column sums + S.  grid 64 x 256 thr.
__global__ void k_prep(const float* __restrict__ src, const float* __restrict__ tgt) {
    __shared__ float shc[8][DDIM];
    __shared__ float shs[8];
    int tid = threadIdx.x;
    int warp = tid >> 5, lane = tid & 31;

    float cs0 = 0.f, cs1 = 0.f, cs2 = 0.f, cs3 = 0.f, sS = 0.f;

    #pragma unroll 4
    for (int it = 0; it < 16; it++) {
        int row = blockIdx.x * 128 + it * 8 + warp;
        const float* p = (row < NHALF) ? (src + (size_t)row * DDIM)
                                       : (tgt + (size_t)(row - NHALF) * DDIM);
        float4 v = ((const float4*)p)[lane];

        cs0 += v.x; cs1 += v.y; cs2 += v.z; cs3 += v.w;

        float sq = v.x * v.x + v.y * v.y + v.z * v.z + v.w * v.w;
        #pragma unroll
        for (int o = 16; o; o >>= 1) sq += __shfl_xor_sync(0xffffffffu, sq, o);
        if (lane == 0) { g_rowsq[row] = sq; sS += sq; }

        __nv_bfloat16 h0 = __float2bfloat16_rn(v.x);
        __nv_bfloat16 h1 = __float2bfloat16_rn(v.y);
        __nv_bfloat16 h2 = __float2bfloat16_rn(v.z);
        __nv_bfloat16 h3 = __float2bfloat16_rn(v.w);
        __nv_bfloat16 l0 = __float2bfloat16_rn(v.x - __bfloat162float(h0));
        __nv_bfloat16 l1 = __float2bfloat16_rn(v.y - __bfloat162float(h1));
        __nv_bfloat16 l2 = __float2bfloat16_rn(v.z - __bfloat162float(h2));
        __nv_bfloat16 l3 = __float2bfloat16_rn(v.w - __bfloat162float(h3));

        uint2 ph, pl;
        ph.x = (uint32_t)__bfloat16_as_ushort(h0) | ((uint32_t)__bfloat16_as_ushort(h1) << 16);
        ph.y = (uint32_t)__bfloat16_as_ushort(h2) | ((uint32_t)__bfloat16_as_ushort(h3) << 16);
        pl.x = (uint32_t)__bfloat16_as_ushort(l0) | ((uint32_t)__bfloat16_as_ushort(l1) << 16);
        pl.y = (uint32_t)__bfloat16_as_ushort(l2) | ((uint32_t)__bfloat16_as_ushort(l3) << 16);
        *(uint2*)&g_hi[(size_t)row * DDIM + lane * 4] = ph;
        *(uint2*)&g_lo[(size_t)row * DDIM + lane * 4] = pl;
    }

    float4 c4v = make_float4(cs0, cs1, cs2, cs3);
    *(float4*)&shc[warp][lane * 4] = c4v;
    if (lane == 0) shs[warp] = sS;
    __syncthreads();

    if (tid < DDIM) {
        float s = 0.f;
        #pragma unroll
        for (int w = 0; w < 8; w++) s += shc[w][tid];
        atomicAdd(&g_colsum[tid], (double)s);
    }
    if (tid == 0) {
        float s = 0.f;
        #pragma unroll
        for (int w = 0; w < 8; w++) s += shs[w];
        atomicAdd(&g_S, (double)s);
    }
}

__global__ void k_scale() {
    __shared__ double sw[4];
    int t = threadIdx.x, lane = t & 31;
    double c = g_colsum[t];
    double p = c * c;
    #pragma unroll
    for (int o = 16; o; o >>= 1) p += __shfl_xor_sync(0xffffffffu, p, o);
    if (lane == 0) sw[t >> 5] = p;
    __syncthreads();
    if (t == 0) {
        double T2 = sw[0] + sw[1] + sw[2] + sw[3];
        double M = (double)NROWS;
        double bw = (2.0 * M * g_S - 2.0 * T2) / (M * M - M);
        bw = bw / 4.0;                     // KERNEL_MUL^(KERNEL_NUM//2)
        g_c = (float)(1.0 / (16.0 * bw));  // widest kernel coefficient
    }
}

// ================= main kernel =================
__global__ void __launch_bounds__(256, 2)
k_main() {
    extern __shared__ __align__(16) char dsm[];
    uint32_t sb = smem_u32(dsm);

    int tid = threadIdx.x;
    int wid = tid >> 5, lane = tid & 31;

    int pair = blockIdx.x >> 1;
    int half = blockIdx.x & 1;
    int bi = 0, rem = pair;
    while (rem >= NB - bi) { rem -= NB - bi; bi++; }
    int bj = bi + rem;

    int rowA0 = bi * 128;
    int rowB0 = bj * 128 + half * 64;

    // ---- pipelined staging: 4 k-chunk commit groups ----
    #pragma unroll
    for (int c = 0; c < 4; c++) {
        #pragma unroll
        for (int i = 0; i < 4; i++) {           // A hi+lo: 1024 x 16B
            int f = tid + i * 256;
            int hl = f >> 9;
            int q = f & 511;
            int r = q >> 2, c4 = q & 3;
            uint32_t dst = sb + (hl ? OFF_A_LO : OFF_A_HI)
                         + (uint32_t)(r * SROW + c * 64 + c4 * 16);
            const __nv_bfloat16* srcb = (hl ? g_lo : g_hi)
                + (size_t)(rowA0 + r) * DDIM + c * 32 + c4 * 8;
            cp_async16(dst, srcb);
        }
        #pragma unroll
        for (int i = 0; i < 2; i++) {           // B hi+lo: 512 x 16B
            int f = tid + i * 256;
            int hl = f >> 8;
            int q = f & 255;
            int r = q >> 2, c4 = q & 3;
            uint32_t dst = sb + (hl ? OFF_B_LO : OFF_B_HI)
                         + (uint32_t)(r * SROW + c * 64 + c4 * 16);
            const __nv_bfloat16* srcb = (hl ? g_lo : g_hi)
                + (size_t)(rowB0 + r) * DDIM + c * 32 + c4 * 8;
            cp_async16(dst, srcb);
        }
        cp_commit();
    }

    const float L2E = 1.4426950408889634f;
    float cfac = g_c;
    float nc2 = -cfac * L2E;
    if (tid < 64) {
        ((float*)(dsm + OFF_Q))[tid] = nc2 * g_rowsq[rowB0 + tid];
    }

    // ---- warp-level GEMM: warp grid 4x2, warp tile 32x32 ----
    int warp_m = wid & 3;
    int warp_n = wid >> 2;
    int R = warp_m * 32;
    int C = warp_n * 32;

    int mat = lane >> 3;
    int rin = lane & 7;
    int mrow = (mat & 1) * 8 + rin;
    int mc16 = (mat >> 1) * 16;

    uint32_t aHiAddr[2], aLoAddr[2], bHiAddr[2], bLoAddr[2];
    #pragma unroll
    for (int mt = 0; mt < 2; mt++) {
        uint32_t off = (uint32_t)((R + mt * 16 + mrow) * SROW + mc16);
        aHiAddr[mt] = sb + OFF_A_HI + off;
        aLoAddr[mt] = sb + OFF_A_LO + off;
    }
    #pragma unroll
    for (int np = 0; np < 2; np++) {
        uint32_t off = (uint32_t)((C + np * 16 + mrow) * SROW + mc16);
        bHiAddr[np] = sb + OFF_B_HI + off;
        bLoAddr[np] = sb + OFF_B_LO + off;
    }

    float acc[2][4][4];
    #pragma unroll
    for (int mt = 0; mt < 2; mt++)
        #pragma unroll
        for (int nt = 0; nt < 4; nt++)
            #pragma unroll
            for (int r = 0; r < 4; r++) acc[mt][nt][r] = 0.0f;

    #pragma unroll
    for (int c = 0; c < 4; c++) {
        if (c == 0) cp_wait<3>();
        else if (c == 1) cp_wait<2>();
        else if (c == 2) cp_wait<1>();
        else cp_wait<0>();
        __syncthreads();

        #pragma unroll
        for (int ks2 = 0; ks2 < 2; ks2++) {
            uint32_t ko = (uint32_t)(c * 2 + ks2) * 32;
            uint32_t ah[2][4], al[2][4];
            uint32_t bh[4][2], bl[4][2];
            #pragma unroll
            for (int mt = 0; mt < 2; mt++) {
                LDSM_X4(ah[mt][0], ah[mt][1], ah[mt][2], ah[mt][3], aHiAddr[mt] + ko);
                LDSM_X4(al[mt][0], al[mt][1], al[mt][2], al[mt][3], aLoAddr[mt] + ko);
            }
            #pragma unroll
            for (int np = 0; np < 2; np++) {
                uint32_t r0, r1, r2, r3;
                LDSM_X4(r0, r1, r2, r3, bHiAddr[np] + ko);
                bh[np * 2 + 0][0] = r0; bh[np * 2 + 0][1] = r2;
                bh[np * 2 + 1][0] = r1; bh[np * 2 + 1][1] = r3;
                LDSM_X4(r0, r1, r2, r3, bLoAddr[np] + ko);
                bl[np * 2 + 0][0] = r0; bl[np * 2 + 0][1] = r2;
                bl[np * 2 + 1][0] = r1; bl[np * 2 + 1][1] = r3;
            }
            #pragma unroll
            for (int mt = 0; mt < 2; mt++) {
                #pragma unroll
                for (int nt = 0; nt < 4; nt++) {
                    MMA_BF16(acc[mt][nt], ah[mt], bh[nt]);
                    MMA_BF16(acc[mt][nt], ah[mt], bl[nt]);
                    MMA_BF16(acc[mt][nt], al[mt], bh[nt]);
                }
            }
        }
    }

    // ---- fused RBF epilogue ----
    float c2s = 2.0f * cfac * L2E;
    u64t c22 = pk(c2s, c2s);
    const float* qv = (const float*)(dsm + OFF_Q);

    u64t kA2[2][2];
    #pragma unroll
    for (int mt = 0; mt < 2; mt++)
        #pragma unroll
        for (int h = 0; h < 2; h++) {
            float kv = nc2 * g_rowsq[rowA0 + R + mt * 16 + h * 8 + (lane >> 2)];
            kA2[mt][h] = pk(kv, kv);
        }
    u64t q2[4];
    #pragma unroll
    for (int nt = 0; nt < 4; nt++)
        q2[nt] = *(const u64t*)(qv + C + nt * 8 + 2 * (lane & 3));

    u64t acc2 = pk(0.0f, 0.0f);
    #pragma unroll
    for (int mt = 0; mt < 2; mt++) {
        #pragma unroll
        for (int nt = 0; nt < 4; nt++) {
            #pragma unroll
            for (int h = 0; h < 2; h++) {
                u64t d2 = pk(acc[mt][nt][h * 2], acc[mt][nt][h * 2 + 1]);
                u64t arg = pk_fma(d2, c22, pk_add(q2[nt], kA2[mt][h]));
                float ax, bx; unpk(ax, bx, arg);
                u64t a1 = pk(ex2f(ax), ex2f(bx));
                u64t a2 = pk_mul(a1, a1);
                u64t a4 = pk_mul(a2, a2);
                u64t a8 = pk_mul(a4, a4);
                u64t u  = pk_fma(a8, a8, a8);   // a8 + a16
                u64t s  = pk_add(pk_add(u, a4), pk_add(a2, a1));
                acc2 = pk_add(acc2, s);
            }
        }
    }
    float plo, phi; unpk(plo, phi, acc2);
    float part = plo + phi;

    float w = ((bi < NB / 2) == (bj < NB / 2)) ? 1.0f : -1.0f;
    if (bi != bj) w *= 2.0f;
    part *= w;

    float* red = (float*)(dsm + OFF_RED);
    red[tid] = part;
    __syncthreads();
    #pragma unroll
    for (int s = 128; s > 0; s >>= 1) {
        if (tid < s) red[tid] += red[tid + s];
        __syncthreads();
    }
    if (tid == 0) atomicAdd(&g_acc, (double)red[0]);
}

__global__ void k_final(float* out) {
    out[0] = (float)(g_acc / ((double)NHALF * (double)NHALF));
}

extern "C" void kernel_launch(void* const* d_in, const int* in_sizes, int n_in,
                              void* d_out, int out_size) {
    const float* src = (const float*)d_in[0];
    const float* tgt = (const float*)d_in[1];
    float* out = (float*)d_out;

    cudaFuncSetAttribute(k_main, cudaFuncAttributeMaxDynamicSharedMemorySize, SMEM_DYN);

    k_init<<<1, 128>>>();
    k_prep<<<64, 256>>>(src, tgt);
    k_scale<<<1, DDIM>>>();
    k_main<<<NCTAS, 256, SMEM_DYN>>>();
    k_final<<<1, 1>>>(out);
}

// round 8
// speedup vs baseline: 1.2898x; 1.2898x over previous
#include <cuda_runtime.h>
#include <cuda_bf16.h>
#include <cstdint>

// MMD loss: persistent double-buffered bf16 3-term split Gram (mma.sync)
// over the upper block-triangle, fused single-exp 5-kernel RBF mixture.

#define NROWS 8192
#define NHALF 4096
#define DDIM  128

#define NB 64                        // 128-row blocks
#define NPAIRS (NB * (NB + 1) / 2)   // 2080
#define NTILES (NPAIRS * 2)          // 4160 (128x64 tiles)
#define NSM 148
#define NTHR 512

#define SROW 272                     // padded row stride bytes
#define A_BYTES (128 * SROW)         // 34816
#define B_BYTES (64 * SROW)          // 17408
#define OFF_AH 0
#define OFF_AL A_BYTES
#define OFF_BH (2 * A_BYTES)
#define OFF_BL (2 * A_BYTES + B_BYTES)
#define BUF_SZ (2 * A_BYTES + 2 * B_BYTES)   // 104448
#define OFF_RED (2 * BUF_SZ)                 // 208896
#define SMEM_DYN (OFF_RED + NTHR * 4)        // 210944

// ---- device scratch ----
__device__ double g_S;
__device__ double g_colsum[DDIM];
__device__ float  g_rowsq[NROWS];
__device__ double g_acc;
__device__ float  g_c;
__device__ __align__(16) __nv_bfloat16 g_hi[NROWS * DDIM];
__device__ __align__(16) __nv_bfloat16 g_lo[NROWS * DDIM];

// ================= helpers =================
__device__ __forceinline__ uint32_t smem_u32(const void* p) {
    uint32_t a;
    asm("{ .reg .u64 t; cvta.to.shared.u64 t, %1; cvt.u32.u64 %0, t; }" : "=r"(a) : "l"(p));
    return a;
}
__device__ __forceinline__ float ex2f(float x) {
    float r; asm("ex2.approx.ftz.f32 %0, %1;" : "=f"(r) : "f"(x));
    return r;
}
__device__ __forceinline__ void cp_async16(uint32_t dst, const void* src) {
    asm volatile("cp.async.cg.shared.global [%0], [%1], 16;" :: "r"(dst), "l"(src) : "memory");
}
__device__ __forceinline__ void cp_commit() {
    asm volatile("cp.async.commit_group;" ::: "memory");
}
template <int N>
__device__ __forceinline__ void cp_wait() {
    asm volatile("cp.async.wait_group %0;" :: "n"(N) : "memory");
}

#define LDSM_X4(r0, r1, r2, r3, addr) \
    asm volatile("ldmatrix.sync.aligned.m8n8.x4.shared.b16 {%0,%1,%2,%3}, [%4];" \
        : "=r"(r0), "=r"(r1), "=r"(r2), "=r"(r3) : "r"(addr))

#define MMA_BF16(d, a, b) \
    asm volatile("mma.sync.aligned.m16n8k16.row.col.f32.bf16.bf16.f32 " \
        "{%0,%1,%2,%3}, {%4,%5,%6,%7}, {%8,%9}, {%0,%1,%2,%3};" \
        : "+f"((d)[0]), "+f"((d)[1]), "+f"((d)[2]), "+f"((d)[3]) \
        : "r"((a)[0]), "r"((a)[1]), "r"((a)[2]), "r"((a)[3]), "r"((b)[0]), "r"((b)[1]))

// f32x2 packed ops
typedef unsigned long long u64t;
__device__ __forceinline__ u64t pk(float a, float b) {
    u64t r; asm("mov.b64 %0, {%1, %2};" : "=l"(r) : "f"(a), "f"(b)); return r;
}
__device__ __forceinline__ void unpk(float& a, float& b, u64t v) {
    asm("mov.b64 {%0, %1}, %2;" : "=f"(a), "=f"(b) : "l"(v));
}
__device__ __forceinline__ u64t pk_fma(u64t a, u64t b, u64t c) {
    u64t r; asm("fma.rn.f32x2 %0, %1, %2, %3;" : "=l"(r) : "l"(a), "l"(b), "l"(c)); return r;
}
__device__ __forceinline__ u64t pk_mul(u64t a, u64t b) {
    u64t r; asm("mul.rn.f32x2 %0, %1, %2;" : "=l"(r) : "l"(a), "l"(b)); return r;
}
__device__ __forceinline__ u64t pk_add(u64t a, u64t b) {
    u64t r; asm("add.rn.f32x2 %0, %1, %2;" : "=l"(r) : "l"(a), "l"(b)); return r;
}

// ================= prep kernels =================
__global__ void k_init() {
    int t = threadIdx.x;
    if (t == 0) { g_S = 0.0; g_acc = 0.0; }
    if (t < DDIM) g_colsum[t] = 0.0;
}

__global__ void k_prep(const float* __restrict__ src, const float* __restrict__ tgt) {
    __shared__ float shc[8][DDIM];
    __shared__ float shs[8];
    int tid = threadIdx.x;
    int warp = tid >> 5, lane = tid & 31;

    float cs0 = 0.f, cs1 = 0.f, cs2 = 0.f, cs3 = 0.f, sS = 0.f;

    #pragma unroll 4
    for (int it = 0; it < 16; it++) {
        int row = blockIdx.x * 128 + it * 8 + warp;
        const float* p = (row < NHALF) ? (src + (size_t)row * DDIM)
                                       : (tgt + (size_t)(row - NHALF) * DDIM);
        float4 v = ((const float4*)p)[lane];

        cs0 += v.x; cs1 += v.y; cs2 += v.z; cs3 += v.w;

        float sq = v.x * v.x + v.y * v.y + v.z * v.z + v.w * v.w;
        #pragma unroll
        for (int o = 16; o; o >>= 1) sq += __shfl_xor_sync(0xffffffffu, sq, o);
        if (lane == 0) { g_rowsq[row] = sq; sS += sq; }

        __nv_bfloat16 h0 = __float2bfloat16_rn(v.x);
        __nv_bfloat16 h1 = __float2bfloat16_rn(v.y);
        __nv_bfloat16 h2 = __float2bfloat16_rn(v.z);
        __nv_bfloat16 h3 = __float2bfloat16_rn(v.w);
        __nv_bfloat16 l0 = __float2bfloat16_rn(v.x - __bfloat162float(h0));
        __nv_bfloat16 l1 = __float2bfloat16_rn(v.y - __bfloat162float(h1));
        __nv_bfloat16 l2 = __float2bfloat16_rn(v.z - __bfloat162float(h2));
        __nv_bfloat16 l3 = __float2bfloat16_rn(v.w - __bfloat162float(h3));

        uint2 ph, pl;
        ph.x = (uint32_t)__bfloat16_as_ushort(h0) | ((uint32_t)__bfloat16_as_ushort(h1) << 16);
        ph.y = (uint32_t)__bfloat16_as_ushort(h2) | ((uint32_t)__bfloat16_as_ushort(h3) << 16);
        pl.x = (uint32_t)__bfloat16_as_ushort(l0) | ((uint32_t)__bfloat16_as_ushort(l1) << 16);
        pl.y = (uint32_t)__bfloat16_as_ushort(l2) | ((uint32_t)__bfloat16_as_ushort(l3) << 16);
        *(uint2*)&g_hi[(size_t)row * DDIM + lane * 4] = ph;
        *(uint2*)&g_lo[(size_t)row * DDIM + lane * 4] = pl;
    }

    *(float4*)&shc[warp][lane * 4] = make_float4(cs0, cs1, cs2, cs3);
    if (lane == 0) shs[warp] = sS;
    __syncthreads();

    if (tid < DDIM) {
        float s = 0.f;
        #pragma unroll
        for (int w = 0; w < 8; w++) s += shc[w][tid];
        atomicAdd(&g_colsum[tid], (double)s);
    }
    if (tid == 0) {
        float s = 0.f;
        #pragma unroll
        for (int w = 0; w < 8; w++) s += shs[w];
        atomicAdd(&g_S, (double)s);
    }
}

__global__ void k_scale() {
    __shared__ double sw[4];
    int t = threadIdx.x, lane = t & 31;
    double c = g_colsum[t];
    double p = c * c;
    #pragma unroll
    for (int o = 16; o; o >>= 1) p += __shfl_xor_sync(0xffffffffu, p, o);
    if (lane == 0) sw[t >> 5] = p;
    __syncthreads();
    if (t == 0) {
        double T2 = sw[0] + sw[1] + sw[2] + sw[3];
        double M = (double)NROWS;
        double bw = (2.0 * M * g_S - 2.0 * T2) / (M * M - M);
        bw = bw / 4.0;
        g_c = (float)(1.0 / (16.0 * bw));
    }
}

// ================= main persistent kernel =================
__device__ __forceinline__ void decode_tile(int t, int& rA, int& rB, float& w) {
    int pair = t >> 1, half = t & 1;
    int bi = 0, rem = pair;
    while (rem >= NB - bi) { rem -= NB - bi; bi++; }
    int bj = bi + rem;
    rA = bi * 128;
    rB = bj * 128 + half * 64;
    w = ((bi < NB / 2) == (bj < NB / 2)) ? 1.0f : -1.0f;
    if (bi != bj) w *= 2.0f;
}

__device__ __forceinline__ void prefetch_tile(uint32_t sb, int buf, int rA0, int rB0, int tid) {
    uint32_t bb = sb + buf * BUF_SZ;
    #pragma unroll
    for (int i = 0; i < 8; i++) {               // A hi+lo: 4096 x 16B
        int a = tid + i * NTHR;
        int hl = a >> 11;
        int q = a & 2047;
        int r = q >> 4, c16 = q & 15;
        uint32_t dst = bb + (hl ? OFF_AL : OFF_AH) + (uint32_t)(r * SROW + c16 * 16);
        const __nv_bfloat16* s = (hl ? g_lo : g_hi) + (size_t)(rA0 + r) * DDIM + c16 * 8;
        cp_async16(dst, s);
    }
    #pragma unroll
    for (int i = 0; i < 4; i++) {               // B hi+lo: 2048 x 16B
        int b = tid + i * NTHR;
        int hl = b >> 10;
        int q = b & 1023;
        int r = q >> 4, c16 = q & 15;
        uint32_t dst = bb + (hl ? OFF_BL : OFF_BH) + (uint32_t)(r * SROW + c16 * 16);
        const __nv_bfloat16* s = (hl ? g_lo : g_hi) + (size_t)(rB0 + r) * DDIM + c16 * 8;
        cp_async16(dst, s);
    }
    cp_commit();
}

__global__ void __launch_bounds__(NTHR, 1)
k_main() {
    extern __shared__ __align__(16) char dsm[];
    uint32_t sb = smem_u32(dsm);

    int tid = threadIdx.x;
    int wid = tid >> 5, lane = tid & 31;

    // warp tile 32x16 in a 4x4 warp grid
    int R = (wid & 3) * 32;
    int C = (wid >> 2) * 16;

    int mat = lane >> 3;
    int rin = lane & 7;
    int mrow = (mat & 1) * 8 + rin;
    int mc16 = (mat >> 1) * 16;

    // buffer-relative fragment addresses
    uint32_t aOffH[2], aOffL[2];
    #pragma unroll
    for (int mt = 0; mt < 2; mt++) {
        uint32_t off = (uint32_t)((R + mt * 16 + mrow) * SROW + mc16);
        aOffH[mt] = OFF_AH + off;
        aOffL[mt] = OFF_AL + off;
    }
    uint32_t bOffH = OFF_BH + (uint32_t)((C + mrow) * SROW + mc16);
    uint32_t bOffL = OFF_BL + (uint32_t)((C + mrow) * SROW + mc16);

    const float L2E = 1.4426950408889634f;
    float cfac = g_c;
    float nc2 = -cfac * L2E;
    u64t nc22 = pk(nc2, nc2);
    float c2s = 2.0f * cfac * L2E;
    u64t c22 = pk(c2s, c2s);

    int t = blockIdx.x;
    int rA0, rB0; float w;
    decode_tile(t, rA0, rB0, w);
    prefetch_tile(sb, 0, rA0, rB0, tid);

    float total = 0.0f;
    int buf = 0;

    while (true) {
        int tn = t + NSM;
        bool hasnext = (tn < NTILES);
        int rA0n, rB0n; float wn;
        if (hasnext) {
            decode_tile(tn, rA0n, rB0n, wn);
            prefetch_tile(sb, buf ^ 1, rA0n, rB0n, tid);
            cp_wait<1>();
        } else {
            cp_wait<0>();
        }
        __syncthreads();

        uint32_t bb = sb + buf * BUF_SZ;
        uint32_t aH0 = bb + aOffH[0], aH1 = bb + aOffH[1];
        uint32_t aL0 = bb + aOffL[0], aL1 = bb + aOffL[1];
        uint32_t bH = bb + bOffH, bL = bb + bOffL;

        float acc[2][2][4];
        #pragma unroll
        for (int mt = 0; mt < 2; mt++)
            #pragma unroll
            for (int nt = 0; nt < 2; nt++)
                #pragma unroll
                for (int r = 0; r < 4; r++) acc[mt][nt][r] = 0.0f;

        #pragma unroll
        for (int ks = 0; ks < 8; ks++) {
            uint32_t ko = (uint32_t)ks * 32;
            uint32_t ah[2][4], al[2][4], bh[2][2], bl[2][2];
            LDSM_X4(ah[0][0], ah[0][1], ah[0][2], ah[0][3], aH0 + ko);
            LDSM_X4(ah[1][0], ah[1][1], ah[1][2], ah[1][3], aH1 + ko);
            LDSM_X4(al[0][0], al[0][1], al[0][2], al[0][3], aL0 + ko);
            LDSM_X4(al[1][0], al[1][1], al[1][2], al[1][3], aL1 + ko);
            {
                uint32_t r0, r1, r2, r3;
                LDSM_X4(r0, r1, r2, r3, bH + ko);
                bh[0][0] = r0; bh[0][1] = r2;
                bh[1][0] = r1; bh[1][1] = r3;
                LDSM_X4(r0, r1, r2, r3, bL + ko);
                bl[0][0] = r0; bl[0][1] = r2;
                bl[1][0] = r1; bl[1][1] = r3;
            }
            #pragma unroll
            for (int mt = 0; mt < 2; mt++) {
                #pragma unroll
                for (int nt = 0; nt < 2; nt++) {
                    MMA_BF16(acc[mt][nt], ah[mt], bh[nt]);
                    MMA_BF16(acc[mt][nt], ah[mt], bl[nt]);
                    MMA_BF16(acc[mt][nt], al[mt], bh[nt]);
                }
            }
        }

        // ---- fused RBF epilogue (register data, broadcast LDG for norms) ----
        u64t kA2[2][2];
        #pragma unroll
        for (int mt = 0; mt < 2; mt++)
            #pragma unroll
            for (int h = 0; h < 2; h++) {
                float kv = nc2 * g_rowsq[rA0 + R + mt * 16 + h * 8 + (lane >> 2)];
                kA2[mt][h] = pk(kv, kv);
            }
        u64t q2[2];
        #pragma unroll
        for (int nt = 0; nt < 2; nt++)
            q2[nt] = *(const u64t*)(g_rowsq + rB0 + C + nt * 8 + 2 * (lane & 3));

        u64t acc2 = pk(0.0f, 0.0f);
        #pragma unroll
        for (int mt = 0; mt < 2; mt++) {
            #pragma unroll
            for (int nt = 0; nt < 2; nt++) {
                u64t base2 = pk_fma(q2[nt], nc22, pk(0.f, 0.f));
                #pragma unroll
                for (int h = 0; h < 2; h++) {
                    u64t d2 = pk(acc[mt][nt][h * 2], acc[mt][nt][h * 2 + 1]);
                    u64t arg = pk_fma(d2, c22, pk_add(base2, kA2[mt][h]));
                    float ax, bx; unpk(ax, bx, arg);
                    u64t a1 = pk(ex2f(ax), ex2f(bx));
                    u64t a2 = pk_mul(a1, a1);
                    u64t a4 = pk_mul(a2, a2);
                    u64t a8 = pk_mul(a4, a4);
                    u64t u  = pk_fma(a8, a8, a8);   // a8 + a16
                    u64t s  = pk_add(pk_add(u, a4), pk_add(a2, a1));
                    acc2 = pk_add(acc2, s);
                }
            }
        }
        float plo, phi; unpk(plo, phi, acc2);
        total += w * (plo + phi);

        __syncthreads();   // all warps done reading buf before it is overwritten

        if (!hasnext) break;
        t = tn; rA0 = rA0n; rB0 = rB0n; w = wn;
        buf ^= 1;
    }

    // ---- one block reduction + one atomic per CTA ----
    float* red = (float*)(dsm + OFF_RED);
    red[tid] = total;
    __syncthreads();
    #pragma unroll
    for (int s = NTHR / 2; s > 0; s >>= 1) {
        if (tid < s) red[tid] += red[tid + s];
        __syncthreads();
    }
    if (tid == 0) atomicAdd(&g_acc, (double)red[0]);
}

__global__ void k_final(float* out) {
    out[0] = (float)(g_acc / ((double)NHALF * (double)NHALF));
}

extern "C" void kernel_launch(void* const* d_in, const int* in_sizes, int n_in,
                              void* d_out, int out_size) {
    const float* src = (const float*)d_in[0];
    const float* tgt = (const float*)d_in[1];
    float* out = (float*)d_out;

    cudaFuncSetAttribute(k_main, cudaFuncAttributeMaxDynamicSharedMemorySize, SMEM_DYN);

    k_init<<<1, 128>>>();
    k_prep<<<64, 256>>>(src, tgt);
    k_scale<<<1, DDIM>>>();
    k_main<<<NSM, NTHR, SMEM_DYN>>>();
    k_final<<<1, 1>>>(out);
}

// round 10
// speedup vs baseline: 1.7605x; 1.3649x over previous
#include <cuda_runtime.h>
#include <cuda_bf16.h>
#include <cstdint>

// MMD loss: persistent run-ordered bf16 3-term split Gram (mma.sync) with
// A-block reuse + 3-deep cp.async B pipeline + XOR-swizzled smem, fused
// single-exp 5-kernel RBF mixture epilogue. 3 launches total.

#define NROWS 8192
#define NHALF 4096
#define DDIM  128
#define NB    64
#define NTILES 4160
#define NCTA  296
#define L2E   1.4426950408889634f

// smem layout (per CTA): A hi 32768 | A lo 32768 | 3 x B buf (hi 8192 + lo 8192)
#define A_HI_OFF 0
#define A_LO_OFF 32768
#define B_BASE   65536
#define B_STRIDE 16384
#define SMEM_DYN (B_BASE + 3 * B_STRIDE)   // 114688

// ---- device scratch ----
__device__ double g_S;
__device__ double g_colsum[DDIM];
__device__ float  g_rowsq[NROWS];
__device__ double g_acc;
__device__ float  g_c;
__device__ unsigned g_done_prep;
__device__ unsigned g_done_main;
__device__ __align__(16) __nv_bfloat16 g_hi[NROWS * DDIM];
__device__ __align__(16) __nv_bfloat16 g_lo[NROWS * DDIM];

// ================= helpers =================
__device__ __forceinline__ uint32_t smem_u32(const void* p) {
    uint32_t a;
    asm("{ .reg .u64 t; cvta.to.shared.u64 t, %1; cvt.u32.u64 %0, t; }" : "=r"(a) : "l"(p));
    return a;
}
__device__ __forceinline__ float ex2f(float x) {
    float r; asm("ex2.approx.ftz.f32 %0, %1;" : "=f"(r) : "f"(x));
    return r;
}
__device__ __forceinline__ void cp_async16(uint32_t dst, const void* src) {
    asm volatile("cp.async.cg.shared.global [%0], [%1], 16;" :: "r"(dst), "l"(src) : "memory");
}
__device__ __forceinline__ void cp_commit() {
    asm volatile("cp.async.commit_group;" ::: "memory");
}
template <int N>
__device__ __forceinline__ void cp_wait() {
    asm volatile("cp.async.wait_group %0;" :: "n"(N) : "memory");
}

#define LDSM_X4(r0, r1, r2, r3, addr) \
    asm volatile("ldmatrix.sync.aligned.m8n8.x4.shared.b16 {%0,%1,%2,%3}, [%4];" \
        : "=r"(r0), "=r"(r1), "=r"(r2), "=r"(r3) : "r"(addr))

#define MMA_BF16(d, a, b) \
    asm volatile("mma.sync.aligned.m16n8k16.row.col.f32.bf16.bf16.f32 " \
        "{%0,%1,%2,%3}, {%4,%5,%6,%7}, {%8,%9}, {%0,%1,%2,%3};" \
        : "+f"((d)[0]), "+f"((d)[1]), "+f"((d)[2]), "+f"((d)[3]) \
        : "r"((a)[0]), "r"((a)[1]), "r"((a)[2]), "r"((a)[3]), "r"((b)[0]), "r"((b)[1]))

typedef unsigned long long u64t;
__device__ __forceinline__ u64t pk(float a, float b) {
    u64t r; asm("mov.b64 %0, {%1, %2};" : "=l"(r) : "f"(a), "f"(b)); return r;
}
__device__ __forceinline__ void unpk(float& a, float& b, u64t v) {
    asm("mov.b64 {%0, %1}, %2;" : "=f"(a), "=f"(b) : "l"(v));
}
__device__ __forceinline__ u64t pk_fma(u64t a, u64t b, u64t c) {
    u64t r; asm("fma.rn.f32x2 %0, %1, %2, %3;" : "=l"(r) : "l"(a), "l"(b), "l"(c)); return r;
}
__device__ __forceinline__ u64t pk_mul(u64t a, u64t b) {
    u64t r; asm("mul.rn.f32x2 %0, %1, %2;" : "=l"(r) : "l"(a), "l"(b)); return r;
}
__device__ __forceinline__ u64t pk_add(u64t a, u64t b) {
    u64t r; asm("add.rn.f32x2 %0, %1, %2;" : "=l"(r) : "l"(a), "l"(b)); return r;
}

// ================= prep kernels =================
__global__ void k_init() {
    int t = threadIdx.x;
    if (t == 0) { g_S = 0.0; g_acc = 0.0; g_done_prep = 0u; g_done_main = 0u; }
    if (t < DDIM) g_colsum[t] = 0.0;
}

// rowsq + bf16 hi/lo split + column sums + S; last CTA computes g_c.
__global__ void k_prep(const float* __restrict__ src, const float* __restrict__ tgt) {
    __shared__ float shc[8][DDIM];
    __shared__ float shs[8];
    int tid = threadIdx.x;
    int warp = tid >> 5, lane = tid & 31;

    float cs0 = 0.f, cs1 = 0.f, cs2 = 0.f, cs3 = 0.f, sS = 0.f;

    #pragma unroll 4
    for (int it = 0; it < 8; it++) {
        int row = blockIdx.x * 64 + it * 8 + warp;
        const float* p = (row < NHALF) ? (src + (size_t)row * DDIM)
                                       : (tgt + (size_t)(row - NHALF) * DDIM);
        float4 v = ((const float4*)p)[lane];

        cs0 += v.x; cs1 += v.y; cs2 += v.z; cs3 += v.w;

        float sq = v.x * v.x + v.y * v.y + v.z * v.z + v.w * v.w;
        #pragma unroll
        for (int o = 16; o; o >>= 1) sq += __shfl_xor_sync(0xffffffffu, sq, o);
        if (lane == 0) { g_rowsq[row] = sq; sS += sq; }

        __nv_bfloat16 h0 = __float2bfloat16_rn(v.x);
        __nv_bfloat16 h1 = __float2bfloat16_rn(v.y);
        __nv_bfloat16 h2 = __float2bfloat16_rn(v.z);
        __nv_bfloat16 h3 = __float2bfloat16_rn(v.w);
        __nv_bfloat16 l0 = __float2bfloat16_rn(v.x - __bfloat162float(h0));
        __nv_bfloat16 l1 = __float2bfloat16_rn(v.y - __bfloat162float(h1));
        __nv_bfloat16 l2 = __float2bfloat16_rn(v.z - __bfloat162float(h2));
        __nv_bfloat16 l3 = __float2bfloat16_rn(v.w - __bfloat162float(h3));

        uint2 ph, pl;
        ph.x = (uint32_t)__bfloat16_as_ushort(h0) | ((uint32_t)__bfloat16_as_ushort(h1) << 16);
        ph.y = (uint32_t)__bfloat16_as_ushort(h2) | ((uint32_t)__bfloat16_as_ushort(h3) << 16);
        pl.x = (uint32_t)__bfloat16_as_ushort(l0) | ((uint32_t)__bfloat16_as_ushort(l1) << 16);
        pl.y = (uint32_t)__bfloat16_as_ushort(l2) | ((uint32_t)__bfloat16_as_ushort(l3) << 16);
        *(uint2*)&g_hi[(size_t)row * DDIM + lane * 4] = ph;
        *(uint2*)&g_lo[(size_t)row * DDIM + lane * 4] = pl;
    }

    *(float4*)&shc[warp][lane * 4] = make_float4(cs0, cs1, cs2, cs3);
    if (lane == 0) shs[warp] = sS;
    __syncthreads();

    if (tid < DDIM) {
        float s = 0.f;
        #pragma unroll
        for (int w = 0; w < 8; w++) s += shc[w][tid];
        atomicAdd(&g_colsum[tid], (double)s);
        __threadfence();
    }
    if (tid == 0) {
        float s = 0.f;
        #pragma unroll
        for (int w = 0; w < 8; w++) s += shs[w];
        atomicAdd(&g_S, (double)s);
        __threadfence();
    }
    __syncthreads();
    if (tid == 0) {
        unsigned tk = atomicAdd(&g_done_prep, 1u);
        if (tk == 127u) {   // last prep CTA computes the bandwidth scale
            __threadfence();
            double T2 = 0.0;
            for (int i = 0; i < DDIM; i++) { double c = g_colsum[i]; T2 += c * c; }
            double M = (double)NROWS;
            double bw = (2.0 * M * g_S - 2.0 * T2) / (M * M - M);
            bw = bw / 4.0;                     // KERNEL_MUL^(KERNEL_NUM//2)
            g_c = (float)(1.0 / (16.0 * bw));  // widest kernel coefficient
        }
    }
}

// ================= main persistent kernel =================
// stage A block (128 rows x 128 dims, hi+lo) with XOR swizzle
__device__ __forceinline__ void stageA(uint32_t sb, int rA0, int tid) {
    #pragma unroll
    for (int i = 0; i < 16; i++) {
        int idx = tid + i * 256;          // 0..4095
        int plane = idx >> 11;
        int q = idx & 2047;
        int r = q >> 4, c = q & 15;
        uint32_t dst = sb + (plane ? A_LO_OFF : A_HI_OFF)
                     + (uint32_t)(r * 256 + (((c & 8) | ((c ^ r) & 7)) * 16));
        const __nv_bfloat16* s = (plane ? g_lo : g_hi) + (size_t)(rA0 + r) * DDIM + c * 8;
        cp_async16(dst, s);
    }
}

// stage one B k-half (64 rows x 64 dims, hi+lo) with XOR swizzle
__device__ __forceinline__ void stageB(uint32_t bb, int rB0, int kh, int tid) {
    #pragma unroll
    for (int i = 0; i < 4; i++) {
        int idx = tid + i * 256;          // 0..1023
        int plane = idx >> 9;
        int q = idx & 511;
        int r = q >> 3, c = q & 7;
        uint32_t dst = bb + (plane ? 8192 : 0)
                     + (uint32_t)(r * 128 + (((c ^ r) & 7) * 16));
        const __nv_bfloat16* s = (plane ? g_lo : g_hi)
            + (size_t)(rB0 + r) * DDIM + kh * 64 + c * 8;
        cp_async16(dst, s);
    }
}

__global__ void __launch_bounds__(256, 2)
k_main(float* __restrict__ out) {
    extern __shared__ __align__(16) char dsm[];
    uint32_t sb = smem_u32(dsm);

    int tid = threadIdx.x;
    int wid = tid >> 5, lane = tid & 31;

    // warp tile 32x32 in a 4x2 warp grid
    int R = (wid & 3) * 32;
    int C = (wid >> 2) * 32;
    int mat = lane >> 3;
    int rin = lane & 7;
    int mrow = (mat & 1) * 8 + rin;
    int csel = mat >> 1;                  // 0/1 -> 16B unit within k16 step

    uint32_t rowAoff[2], nrowoff[2];
    #pragma unroll
    for (int mt = 0; mt < 2; mt++) rowAoff[mt] = (uint32_t)((R + mt * 16 + mrow) * 256);
    #pragma unroll
    for (int np = 0; np < 2; np++) nrowoff[np] = (uint32_t)((C + np * 16 + mrow) * 128);

    float cfac = g_c;
    float nc2 = -cfac * L2E;
    u64t nc22 = pk(nc2, nc2);
    float c2s = 2.0f * cfac * L2E;
    u64t c22 = pk(c2s, c2s);

    // contiguous chunk of the (bi,bj,half)-ordered tile list
    int b = blockIdx.x;
    int t = b * 14 + (b < 16 ? b : 16);
    int tend = t + 14 + (b < 16 ? 1 : 0);

    int pair = t >> 1, half = t & 1;
    int bi = 0, rem = pair;
    while (rem >= NB - bi) { rem -= NB - bi; bi++; }
    int bj = bi + rem;

    float total = 0.0f;

    while (t < tend) {
        // ---- start a run with constant bi: restart pipeline ----
        int rA0 = bi * 128;
        stageA(sb, rA0, tid);
        stageB(sb + B_BASE, bj * 128 + half * 64, 0, tid);
        cp_commit();                                   // group: A + B(t,k0)
        stageB(sb + B_BASE + B_STRIDE, bj * 128 + half * 64, 1, tid);
        cp_commit();                                   // group: B(t,k1)
        int p = 0;

        bool runend = false;
        while (!runend) {
            int rB0 = bj * 128 + half * 64;
            float w = ((bi < NB / 2) == (bj < NB / 2)) ? 1.0f : -1.0f;
            if (bi != bj) w *= 2.0f;

            int halfn = half ^ 1;
            int bjn = bj + (half & 1);
            bool next_in_run = (t + 1 < tend) && !((half == 1) && (bj == NB - 1));
            int rB0n = bjn * 128 + halfn * 64;          // used only if next_in_run

            float acc[2][4][4];
            #pragma unroll
            for (int mt = 0; mt < 2; mt++)
                #pragma unroll
                for (int nt = 0; nt < 4; nt++)
                    #pragma unroll
                    for (int r = 0; r < 4; r++) acc[mt][nt][r] = 0.0f;

            #pragma unroll
            for (int kh = 0; kh < 2; kh++) {
                if (kh == 0 || next_in_run) cp_wait<1>();
                else cp_wait<0>();
                __syncthreads();
                if (next_in_run) {
                    stageB(sb + B_BASE + ((p + 2) % 3) * B_STRIDE, rB0n, kh, tid);
                    cp_commit();
                }
                uint32_t bb = sb + B_BASE + p * B_STRIDE;

                #pragma unroll
                for (int ks = 0; ks < 4; ks++) {
                    int cB = ks * 2 + csel;
                    uint32_t swz = (uint32_t)(((cB ^ rin) & 7) * 16);
                    uint32_t aoff = (uint32_t)(kh * 128) + swz;

                    uint32_t ah[2][4], al[2][4], bh[4][2], bl[4][2];
                    #pragma unroll
                    for (int mt = 0; mt < 2; mt++) {
                        LDSM_X4(ah[mt][0], ah[mt][1], ah[mt][2], ah[mt][3],
                                sb + A_HI_OFF + rowAoff[mt] + aoff);
                        LDSM_X4(al[mt][0], al[mt][1], al[mt][2], al[mt][3],
                                sb + A_LO_OFF + rowAoff[mt] + aoff);
                    }
                    #pragma unroll
                    for (int np = 0; np < 2; np++) {
                        uint32_t r0, r1, r2, r3;
                        LDSM_X4(r0, r1, r2, r3, bb + nrowoff[np] + swz);
                        bh[np * 2 + 0][0] = r0; bh[np * 2 + 0][1] = r2;
                        bh[np * 2 + 1][0] = r1; bh[np * 2 + 1][1] = r3;
                        LDSM_X4(r0, r1, r2, r3, bb + 8192 + nrowoff[np] + swz);
                        bl[np * 2 + 0][0] = r0; bl[np * 2 + 0][1] = r2;
                        bl[np * 2 + 1][0] = r1; bl[np * 2 + 1][1] = r3;
                    }
                    #pragma unroll
                    for (int mt = 0; mt < 2; mt++) {
                        #pragma unroll
                        for (int nt = 0; nt < 4; nt++) {
                            MMA_BF16(acc[mt][nt], ah[mt], bh[nt]);
                            MMA_BF16(acc[mt][nt], ah[mt], bl[nt]);
                            MMA_BF16(acc[mt][nt], al[mt], bh[nt]);
                        }
                    }
                }
                p = (p + 1) % 3;
            }

            // ---- fused RBF epilogue (no smem, no sync) ----
            u64t kA2[2][2];
            #pragma unroll
            for (int mt = 0; mt < 2; mt++)
                #pragma unroll
                for (int h = 0; h < 2; h++) {
                    float kv = nc2 * g_rowsq[rA0 + R + mt * 16 + h * 8 + (lane >> 2)];
                    kA2[mt][h] = pk(kv, kv);
                }
            u64t acc2 = pk(0.0f, 0.0f);
            #pragma unroll
            for (int nt = 0; nt < 4; nt++) {
                float2 qraw = *(const float2*)&g_rowsq[rB0 + C + nt * 8 + 2 * (lane & 3)];
                u64t base2 = pk_mul(pk(qraw.x, qraw.y), nc22);
                #pragma unroll
                for (int mt = 0; mt < 2; mt++) {
                    #pragma unroll
                    for (int h = 0; h < 2; h++) {
                        u64t d2 = pk(acc[mt][nt][h * 2], acc[mt][nt][h * 2 + 1]);
                        u64t arg = pk_fma(d2, c22, pk_add(base2, kA2[mt][h]));
                        float ax, bx; unpk(ax, bx, arg);
                        u64t a1 = pk(ex2f(ax), ex2f(bx));
                        u64t a2 = pk_mul(a1, a1);
                        u64t a4 = pk_mul(a2, a2);
                        u64t a8 = pk_mul(a4, a4);
                        u64t u  = pk_fma(a8, a8, a8);   // a8 + a16
                        u64t s  = pk_add(pk_add(u, a4), pk_add(a2, a1));
                        acc2 = pk_add(acc2, s);
                    }
                }
            }
            float plo, phi; unpk(plo, phi, acc2);
            total += w * (plo + phi);

            // ---- advance ----
            t++;
            if (next_in_run) {
                bj = bjn; half = halfn;
            } else {
                if (t < tend) { bi++; bj = bi; half = 0; }
                runend = true;
            }
        }
    }

    // ---- final reduction: shfl + per-warp fp64 atomic, last CTA writes out ----
    #pragma unroll
    for (int o = 16; o; o >>= 1) total += __shfl_xor_sync(0xffffffffu, total, o);
    if (lane == 0) {
        atomicAdd(&g_acc, (double)total);
        __threadfence();
    }
    __syncthreads();
    if (tid == 0) {
        unsigned tk = atomicAdd(&g_done_main, 1u);
        if (tk == NCTA - 1) {
            __threadfence();
            out[0] = (float)(g_acc / ((double)NHALF * (double)NHALF));
        }
    }
}

extern "C" void kernel_launch(void* const* d_in, const int* in_sizes, int n_in,
                              void* d_out, int out_size) {
    const float* src = (const float*)d_in[0];
    const float* tgt = (const float*)d_in[1];
    float* out = (float*)d_out;

    cudaFuncSetAttribute(k_main, cudaFuncAttributeMaxDynamicSharedMemorySize, SMEM_DYN);

    k_init<<<1, 128>>>();
    k_prep<<<128, 256>>>(src, tgt);
    k_main<<<NCTA, 256, SMEM_DYN>>>(out);
}

// round 12
// speedup vs baseline: 1.7646x; 1.0023x over previous
#include <cuda_runtime.h>
#include <cuda_bf16.h>
#include <cstdint>

// MMD loss: persistent run-ordered bf16 3-term split Gram (mma.sync) with
// A-block reuse + 3-deep cp.async B pipeline + XOR-swizzled smem, fused
// single-exp 5-kernel RBF mixture epilogue. 2 launches, self-resetting state.

#define NROWS 8192
#define NHALF 4096
#define DDIM  128
#define NB    64
#define NTILES 4160
#define NCTA  296
#define PREP_CTAS 256
#define L2E   1.4426950408889634f

// smem layout (per CTA): A hi 32768 | A lo 32768 | 3 x B buf (hi 8192 + lo 8192)
#define A_HI_OFF 0
#define A_LO_OFF 32768
#define B_BASE   65536
#define B_STRIDE 16384
#define SMEM_DYN (B_BASE + 3 * B_STRIDE)   // 114688

// ---- device scratch (static-init = clean state for replay #1;
//      end-of-kernel cleanup restores it for every subsequent replay) ----
__device__ double g_S = 0.0;
__device__ double g_colsum[DDIM];            // zero-initialized
__device__ float  g_rowsq[NROWS];
__device__ double g_acc;                     // zeroed by last prep CTA each run
__device__ float  g_c;
__device__ unsigned g_done_prep = 0u;        // self-wrapping tickets
__device__ unsigned g_done_main = 0u;
__device__ __align__(16) __nv_bfloat16 g_hi[NROWS * DDIM];
__device__ __align__(16) __nv_bfloat16 g_lo[NROWS * DDIM];

// ================= helpers =================
__device__ __forceinline__ uint32_t smem_u32(const void* p) {
    uint32_t a;
    asm("{ .reg .u64 t; cvta.to.shared.u64 t, %1; cvt.u32.u64 %0, t; }" : "=r"(a) : "l"(p));
    return a;
}
__device__ __forceinline__ float ex2f(float x) {
    float r; asm("ex2.approx.ftz.f32 %0, %1;" : "=f"(r) : "f"(x));
    return r;
}
__device__ __forceinline__ void cp_async16(uint32_t dst, const void* src) {
    asm volatile("cp.async.cg.shared.global [%0], [%1], 16;" :: "r"(dst), "l"(src) : "memory");
}
__device__ __forceinline__ void cp_commit() {
    asm volatile("cp.async.commit_group;" ::: "memory");
}
template <int N>
__device__ __forceinline__ void cp_wait() {
    asm volatile("cp.async.wait_group %0;" :: "n"(N) : "memory");
}

#define LDSM_X4(r0, r1, r2, r3, addr) \
    asm volatile("ldmatrix.sync.aligned.m8n8.x4.shared.b16 {%0,%1,%2,%3}, [%4];" \
        : "=r"(r0), "=r"(r1), "=r"(r2), "=r"(r3) : "r"(addr))

#define MMA_BF16(d, a, b) \
    asm volatile("mma.sync.aligned.m16n8k16.row.col.f32.bf16.bf16.f32 " \
        "{%0,%1,%2,%3}, {%4,%5,%6,%7}, {%8,%9}, {%0,%1,%2,%3};" \
        : "+f"((d)[0]), "+f"((d)[1]), "+f"((d)[2]), "+f"((d)[3]) \
        : "r"((a)[0]), "r"((a)[1]), "r"((a)[2]), "r"((a)[3]), "r"((b)[0]), "r"((b)[1]))

typedef unsigned long long u64t;
__device__ __forceinline__ u64t pk(float a, float b) {
    u64t r; asm("mov.b64 %0, {%1, %2};" : "=l"(r) : "f"(a), "f"(b)); return r;
}
__device__ __forceinline__ void unpk(float& a, float& b, u64t v) {
    asm("mov.b64 {%0, %1}, %2;" : "=f"(a), "=f"(b) : "l"(v));
}
__device__ __forceinline__ u64t pk_fma(u64t a, u64t b, u64t c) {
    u64t r; asm("fma.rn.f32x2 %0, %1, %2, %3;" : "=l"(r) : "l"(a), "l"(b), "l"(c)); return r;
}
__device__ __forceinline__ u64t pk_mul(u64t a, u64t b) {
    u64t r; asm("mul.rn.f32x2 %0, %1, %2;" : "=l"(r) : "l"(a), "l"(b)); return r;
}
__device__ __forceinline__ u64t pk_add(u64t a, u64t b) {
    u64t r; asm("add.rn.f32x2 %0, %1, %2;" : "=l"(r) : "l"(a), "l"(b)); return r;
}

// ================= prep kernel (rowsq + split + colsums + fused scale) ====
__global__ void k_prep(const float* __restrict__ src, const float* __restrict__ tgt) {
    __shared__ float shc[8][DDIM];
    __shared__ float shs[8];
    __shared__ unsigned is_last;
    __shared__ double sred[4];

    int tid = threadIdx.x;
    int warp = tid >> 5, lane = tid & 31;

    float cs0 = 0.f, cs1 = 0.f, cs2 = 0.f, cs3 = 0.f, sS = 0.f;

    #pragma unroll
    for (int it = 0; it < 4; it++) {
        int row = blockIdx.x * 32 + it * 8 + warp;
        const float* p = (row < NHALF) ? (src + (size_t)row * DDIM)
                                       : (tgt + (size_t)(row - NHALF) * DDIM);
        float4 v = ((const float4*)p)[lane];

        cs0 += v.x; cs1 += v.y; cs2 += v.z; cs3 += v.w;

        float sq = v.x * v.x + v.y * v.y + v.z * v.z + v.w * v.w;
        #pragma unroll
        for (int o = 16; o; o >>= 1) sq += __shfl_xor_sync(0xffffffffu, sq, o);
        if (lane == 0) { g_rowsq[row] = sq; sS += sq; }

        __nv_bfloat16 h0 = __float2bfloat16_rn(v.x);
        __nv_bfloat16 h1 = __float2bfloat16_rn(v.y);
        __nv_bfloat16 h2 = __float2bfloat16_rn(v.z);
        __nv_bfloat16 h3 = __float2bfloat16_rn(v.w);
        __nv_bfloat16 l0 = __float2bfloat16_rn(v.x - __bfloat162float(h0));
        __nv_bfloat16 l1 = __float2bfloat16_rn(v.y - __bfloat162float(h1));
        __nv_bfloat16 l2 = __float2bfloat16_rn(v.z - __bfloat162float(h2));
        __nv_bfloat16 l3 = __float2bfloat16_rn(v.w - __bfloat162float(h3));

        uint2 ph, pl;
        ph.x = (uint32_t)__bfloat16_as_ushort(h0) | ((uint32_t)__bfloat16_as_ushort(h1) << 16);
        ph.y = (uint32_t)__bfloat16_as_ushort(h2) | ((uint32_t)__bfloat16_as_ushort(h3) << 16);
        pl.x = (uint32_t)__bfloat16_as_ushort(l0) | ((uint32_t)__bfloat16_as_ushort(l1) << 16);
        pl.y = (uint32_t)__bfloat16_as_ushort(l2) | ((uint32_t)__bfloat16_as_ushort(l3) << 16);
        *(uint2*)&g_hi[(size_t)row * DDIM + lane * 4] = ph;
        *(uint2*)&g_lo[(size_t)row * DDIM + lane * 4] = pl;
    }

    *(float4*)&shc[warp][lane * 4] = make_float4(cs0, cs1, cs2, cs3);
    if (lane == 0) shs[warp] = sS;
    __syncthreads();

    if (tid < DDIM) {
        float s = 0.f;
        #pragma unroll
        for (int w = 0; w < 8; w++) s += shc[w][tid];
        atomicAdd(&g_colsum[tid], (double)s);
        __threadfence();
    }
    if (tid == 0) {
        float s = 0.f;
        #pragma unroll
        for (int w = 0; w < 8; w++) s += shs[w];
        atomicAdd(&g_S, (double)s);
        __threadfence();
    }
    __syncthreads();

    if (tid == 0) {
        unsigned tk = atomicInc(&g_done_prep, PREP_CTAS - 1);  // wraps to 0
        is_last = (tk == PREP_CTAS - 1) ? 1u : 0u;
    }
    __syncthreads();

    if (is_last) {
        __threadfence();
        double p = 0.0;
        if (tid < DDIM) { double c = g_colsum[tid]; p = c * c; }
        #pragma unroll
        for (int o = 16; o; o >>= 1) p += __shfl_xor_sync(0xffffffffu, p, o);
        if (lane == 0 && tid < DDIM) sred[tid >> 5] = p;
        __syncthreads();
        if (tid == 0) {
            double T2 = sred[0] + sred[1] + sred[2] + sred[3];
            double M = (double)NROWS;
            double bw = (2.0 * M * g_S - 2.0 * T2) / (M * M - M);
            bw = bw / 4.0;                     // KERNEL_MUL^(KERNEL_NUM//2)
            g_c = (float)(1.0 / (16.0 * bw));  // widest kernel coefficient
            g_acc = 0.0;                       // reset accumulator for this run
            __threadfence();
        }
    }
}

// ================= main persistent kernel =================
__device__ __forceinline__ void stageA(uint32_t sb, int rA0, int tid) {
    #pragma unroll
    for (int i = 0; i < 16; i++) {
        int idx = tid + i * 256;
        int plane = idx >> 11;
        int q = idx & 2047;
        int r = q >> 4, c = q & 15;
        uint32_t dst = sb + (plane ? A_LO_OFF : A_HI_OFF)
                     + (uint32_t)(r * 256 + (((c & 8) | ((c ^ r) & 7)) * 16));
        const __nv_bfloat16* s = (plane ? g_lo : g_hi) + (size_t)(rA0 + r) * DDIM + c * 8;
        cp_async16(dst, s);
    }
}

__device__ __forceinline__ void stageB(uint32_t bb, int rB0, int kh, int tid) {
    #pragma unroll
    for (int i = 0; i < 4; i++) {
        int idx = tid + i * 256;
        int plane = idx >> 9;
        int q = idx & 511;
        int r = q >> 3, c = q & 7;
        uint32_t dst = bb + (plane ? 8192 : 0)
                     + (uint32_t)(r * 128 + (((c ^ r) & 7) * 16));
        const __nv_bfloat16* s = (plane ? g_lo : g_hi)
            + (size_t)(rB0 + r) * DDIM + kh * 64 + c * 8;
        cp_async16(dst, s);
    }
}

__global__ void __launch_bounds__(256, 2)
k_main(float* __restrict__ out) {
    extern __shared__ __align__(16) char dsm[];
    __shared__ unsigned lastm;
    uint32_t sb = smem_u32(dsm);

    int tid = threadIdx.x;
    int wid = tid >> 5, lane = tid & 31;

    int R = (wid & 3) * 32;
    int C = (wid >> 2) * 32;
    int mat = lane >> 3;
    int rin = lane & 7;
    int mrow = (mat & 1) * 8 + rin;
    int csel = mat >> 1;

    uint32_t rowAoff[2], nrowoff[2];
    #pragma unroll
    for (int mt = 0; mt < 2; mt++) rowAoff[mt] = (uint32_t)((R + mt * 16 + mrow) * 256);
    #pragma unroll
    for (int np = 0; np < 2; np++) nrowoff[np] = (uint32_t)((C + np * 16 + mrow) * 128);

    float cfac = g_c;
    float nc2 = -cfac * L2E;
    u64t nc22 = pk(nc2, nc2);
    float c2s = 2.0f * cfac * L2E;
    u64t c22 = pk(c2s, c2s);

    int b = blockIdx.x;
    int t = b * 14 + (b < 16 ? b : 16);
    int tend = t + 14 + (b < 16 ? 1 : 0);

    int pair = t >> 1, half = t & 1;
    int bi = 0, rem = pair;
    while (rem >= NB - bi) { rem -= NB - bi; bi++; }
    int bj = bi + rem;

    float total = 0.0f;

    while (t < tend) {
        int rA0 = bi * 128;
        stageA(sb, rA0, tid);
        stageB(sb + B_BASE, bj * 128 + half * 64, 0, tid);
        cp_commit();
        stageB(sb + B_BASE + B_STRIDE, bj * 128 + half * 64, 1, tid);
        cp_commit();
        int p = 0;

        bool runend = false;
        while (!runend) {
            int rB0 = bj * 128 + half * 64;
            float w = ((bi < NB / 2) == (bj < NB / 2)) ? 1.0f : -1.0f;
            if (bi != bj) w *= 2.0f;

            int halfn = half ^ 1;
            int bjn = bj + (half & 1);
            bool next_in_run = (t + 1 < tend) && !((half == 1) && (bj == NB - 1));
            int rB0n = bjn * 128 + halfn * 64;

            float acc[2][4][4];
            #pragma unroll
            for (int mt = 0; mt < 2; mt++)
                #pragma unroll
                for (int nt = 0; nt < 4; nt++)
                    #pragma unroll
                    for (int r = 0; r < 4; r++) acc[mt][nt][r] = 0.0f;

            #pragma unroll
            for (int kh = 0; kh < 2; kh++) {
                if (kh == 0 || next_in_run) cp_wait<1>();
                else cp_wait<0>();
                __syncthreads();
                if (next_in_run) {
                    stageB(sb + B_BASE + ((p + 2) % 3) * B_STRIDE, rB0n, kh, tid);
                    cp_commit();
                }
                uint32_t bb = sb + B_BASE + p * B_STRIDE;

                #pragma unroll
                for (int ks = 0; ks < 4; ks++) {
                    int cB = ks * 2 + csel;
                    uint32_t swz = (uint32_t)(((cB ^ rin) & 7) * 16);
                    uint32_t aoff = (uint32_t)(kh * 128) + swz;

                    uint32_t ah[2][4], al[2][4], bh[4][2], bl[4][2];
                    #pragma unroll
                    for (int mt = 0; mt < 2; mt++) {
                        LDSM_X4(ah[mt][0], ah[mt][1], ah[mt][2], ah[mt][3],
                                sb + A_HI_OFF + rowAoff[mt] + aoff);
                        LDSM_X4(al[mt][0], al[mt][1], al[mt][2], al[mt][3],
                                sb + A_LO_OFF + rowAoff[mt] + aoff);
                    }
                    #pragma unroll
                    for (int np = 0; np < 2; np++) {
                        uint32_t r0, r1, r2, r3;
                        LDSM_X4(r0, r1, r2, r3, bb + nrowoff[np] + swz);
                        bh[np * 2 + 0][0] = r0; bh[np * 2 + 0][1] = r2;
                        bh[np * 2 + 1][0] = r1; bh[np * 2 + 1][1] = r3;
                        LDSM_X4(r0, r1, r2, r3, bb + 8192 + nrowoff[np] + swz);
                        bl[np * 2 + 0][0] = r0; bl[np * 2 + 0][1] = r2;
                        bl[np * 2 + 1][0] = r1; bl[np * 2 + 1][1] = r3;
                    }
                    #pragma unroll
                    for (int mt = 0; mt < 2; mt++) {
                        #pragma unroll
                        for (int nt = 0; nt < 4; nt++) {
                            MMA_BF16(acc[mt][nt], ah[mt], bh[nt]);
                            MMA_BF16(acc[mt][nt], ah[mt], bl[nt]);
                            MMA_BF16(acc[mt][nt], al[mt], bh[nt]);
                        }
                    }
                }
                p = (p + 1) % 3;
            }

            // ---- fused RBF epilogue ----
            u64t kA2[2][2];
            #pragma unroll
            for (int mt = 0; mt < 2; mt++)
                #pragma unroll
                for (int h = 0; h < 2; h++) {
                    float kv = nc2 * g_rowsq[rA0 + R + mt * 16 + h * 8 + (lane >> 2)];
                    kA2[mt][h] = pk(kv, kv);
                }
            u64t acc2 = pk(0.0f, 0.0f);
            #pragma unroll
            for (int nt = 0; nt < 4; nt++) {
                float2 qraw = *(const float2*)&g_rowsq[rB0 + C + nt * 8 + 2 * (lane & 3)];
                u64t base2 = pk_mul(pk(qraw.x, qraw.y), nc22);
                #pragma unroll
                for (int mt = 0; mt < 2; mt++) {
                    #pragma unroll
                    for (int h = 0; h < 2; h++) {
                        u64t d2 = pk(acc[mt][nt][h * 2], acc[mt][nt][h * 2 + 1]);
                        u64t arg = pk_fma(d2, c22, pk_add(base2, kA2[mt][h]));
                        float ax, bx; unpk(ax, bx, arg);
                        u64t a1 = pk(ex2f(ax), ex2f(bx));
                        u64t a2 = pk_mul(a1, a1);
                        u64t a4 = pk_mul(a2, a2);
                        u64t a8 = pk_mul(a4, a4);
                        u64t u  = pk_fma(a8, a8, a8);   // a8 + a16
                        u64t s  = pk_add(pk_add(u, a4), pk_add(a2, a1));
                        acc2 = pk_add(acc2, s);
                    }
                }
            }
            float plo, phi; unpk(plo, phi, acc2);
            total += w * (plo + phi);

            t++;
            if (next_in_run) {
                bj = bjn; half = halfn;
            } else {
                if (t < tend) { bi++; bj = bi; half = 0; }
                runend = true;
            }
        }
    }

    // ---- final reduction + self-resetting completion ticket ----
    #pragma unroll
    for (int o = 16; o; o >>= 1) total += __shfl_xor_sync(0xffffffffu, total, o);
    if (lane == 0) {
        atomicAdd(&g_acc, (double)total);
        __threadfence();
    }
    __syncthreads();
    if (tid == 0) {
        unsigned tk = atomicInc(&g_done_main, NCTA - 1);   // wraps to 0
        lastm = (tk == NCTA - 1) ? 1u : 0u;
    }
    __syncthreads();
    if (lastm) {
        __threadfence();
        if (tid == 0) {
            out[0] = (float)(g_acc / ((double)NHALF * (double)NHALF));
            g_S = 0.0;                       // clean state for next replay
        }
        if (tid < DDIM) g_colsum[tid] = 0.0;
    }
}

extern "C" void kernel_launch(void* const* d_in, const int* in_sizes, int n_in,
                              void* d_out, int out_size) {
    const float* src = (const float*)d_in[0];
    const float* tgt = (const float*)d_in[1];
    float* out = (float*)d_out;

    cudaFuncSetAttribute(k_main, cudaFuncAttributeMaxDynamicSharedMemorySize, SMEM_DYN);

    k_prep<<<PREP_CTAS, 256>>>(src, tgt);
    k_main<<<NCTA, 256, SMEM_DYN>>>(out);
}

// round 13
// speedup vs baseline: 1.7722x; 1.0043x over previous
#include <cuda_runtime.h>
#include <cuda_bf16.h>
#include <cstdint>

// MMD loss, single fused persistent kernel: prep (rowsq + bf16 hi/lo split +
// closed-form bandwidth) -> device-wide spin barrier (all 296 CTAs resident)
// -> run-ordered bf16 3-term split Gram (mma.sync) with A-block reuse,
// 3-deep cp.async B pipeline, XOR-swizzled smem, fused single-exp 5-kernel
// RBF mixture epilogue. Self-resetting state for graph replay.

#define NROWS 8192
#define NHALF 4096
#define DDIM  128
#define NB    64
#define NTILES 4160
#define NCTA  296
#define L2E   1.4426950408889634f

// smem layout (per CTA): A hi 32768 | A lo 32768 | 3 x B buf (hi 8192 + lo 8192)
#define A_HI_OFF 0
#define A_LO_OFF 32768
#define B_BASE   65536
#define B_STRIDE 16384
#define SMEM_DYN (B_BASE + 3 * B_STRIDE)   // 114688

// ---- device scratch (static-init = clean state for replay #1;
//      end-of-kernel cleanup restores it for every subsequent replay) ----
__device__ double g_S = 0.0;
__device__ double g_colsum[DDIM];            // zero-initialized
__device__ float  g_rowsq[NROWS];
__device__ double g_acc;                     // zeroed by barrier leader each run
__device__ float  g_c;
__device__ unsigned g_done_prep = 0u;        // self-wrapping tickets
__device__ unsigned g_done_main = 0u;
__device__ unsigned g_go = 0u;               // barrier release flag
__device__ __align__(16) __nv_bfloat16 g_hi[NROWS * DDIM];
__device__ __align__(16) __nv_bfloat16 g_lo[NROWS * DDIM];

// ================= helpers =================
__device__ __forceinline__ uint32_t smem_u32(const void* p) {
    uint32_t a;
    asm("{ .reg .u64 t; cvta.to.shared.u64 t, %1; cvt.u32.u64 %0, t; }" : "=r"(a) : "l"(p));
    return a;
}
__device__ __forceinline__ float ex2f(float x) {
    float r; asm("ex2.approx.ftz.f32 %0, %1;" : "=f"(r) : "f"(x));
    return r;
}
__device__ __forceinline__ void cp_async16(uint32_t dst, const void* src) {
    asm volatile("cp.async.cg.shared.global [%0], [%1], 16;" :: "r"(dst), "l"(src) : "memory");
}
__device__ __forceinline__ void cp_commit() {
    asm volatile("cp.async.commit_group;" ::: "memory");
}
template <int N>
__device__ __forceinline__ void cp_wait() {
    asm volatile("cp.async.wait_group %0;" :: "n"(N) : "memory");
}

#define LDSM_X4(r0, r1, r2, r3, addr) \
    asm volatile("ldmatrix.sync.aligned.m8n8.x4.shared.b16 {%0,%1,%2,%3}, [%4];" \
        : "=r"(r0), "=r"(r1), "=r"(r2), "=r"(r3) : "r"(addr))

#define MMA_BF16(d, a, b) \
    asm volatile("mma.sync.aligned.m16n8k16.row.col.f32.bf16.bf16.f32 " \
        "{%0,%1,%2,%3}, {%4,%5,%6,%7}, {%8,%9}, {%0,%1,%2,%3};" \
        : "+f"((d)[0]), "+f"((d)[1]), "+f"((d)[2]), "+f"((d)[3]) \
        : "r"((a)[0]), "r"((a)[1]), "r"((a)[2]), "r"((a)[3]), "r"((b)[0]), "r"((b)[1]))

typedef unsigned long long u64t;
__device__ __forceinline__ u64t pk(float a, float b) {
    u64t r; asm("mov.b64 %0, {%1, %2};" : "=l"(r) : "f"(a), "f"(b)); return r;
}
__device__ __forceinline__ void unpk(float& a, float& b, u64t v) {
    asm("mov.b64 {%0, %1}, %2;" : "=f"(a), "=f"(b) : "l"(v));
}
__device__ __forceinline__ u64t pk_fma(u64t a, u64t b, u64t c) {
    u64t r; asm("fma.rn.f32x2 %0, %1, %2, %3;" : "=l"(r) : "l"(a), "l"(b), "l"(c)); return r;
}
__device__ __forceinline__ u64t pk_mul(u64t a, u64t b) {
    u64t r; asm("mul.rn.f32x2 %0, %1, %2;" : "=l"(r) : "l"(a), "l"(b)); return r;
}
__device__ __forceinline__ u64t pk_add(u64t a, u64t b) {
    u64t r; asm("add.rn.f32x2 %0, %1, %2;" : "=l"(r) : "l"(a), "l"(b)); return r;
}

// ================= staging =================
__device__ __forceinline__ void stageA(uint32_t sb, int rA0, int tid) {
    #pragma unroll
    for (int i = 0; i < 16; i++) {
        int idx = tid + i * 256;
        int plane = idx >> 11;
        int q = idx & 2047;
        int r = q >> 4, c = q & 15;
        uint32_t dst = sb + (plane ? A_LO_OFF : A_HI_OFF)
                     + (uint32_t)(r * 256 + (((c & 8) | ((c ^ r) & 7)) * 16));
        const __nv_bfloat16* s = (plane ? g_lo : g_hi) + (size_t)(rA0 + r) * DDIM + c * 8;
        cp_async16(dst, s);
    }
}

__device__ __forceinline__ void stageB(uint32_t bb, int rB0, int kh, int tid) {
    #pragma unroll
    for (int i = 0; i < 4; i++) {
        int idx = tid + i * 256;
        int plane = idx >> 9;
        int q = idx & 511;
        int r = q >> 3, c = q & 7;
        uint32_t dst = bb + (plane ? 8192 : 0)
                     + (uint32_t)(r * 128 + (((c ^ r) & 7) * 16));
        const __nv_bfloat16* s = (plane ? g_lo : g_hi)
            + (size_t)(rB0 + r) * DDIM + kh * 64 + c * 8;
        cp_async16(dst, s);
    }
}

// ================= fused kernel =================
__global__ void __launch_bounds__(256, 2)
k_fused(const float* __restrict__ src, const float* __restrict__ tgt,
        float* __restrict__ out) {
    extern __shared__ __align__(16) char dsm[];
    __shared__ unsigned sflag;
    uint32_t sb = smem_u32(dsm);

    int tid = threadIdx.x;
    int wid = tid >> 5, lane = tid & 31;

    // ================= PREP PHASE =================
    // CTAs 0..255 handle 32 rows each; prep scratch lives in dsm (reused later).
    float* shc = (float*)dsm;                    // [8][128]
    float* shs = (float*)(dsm + 4096);           // [8]
    double* sred = (double*)(dsm + 4224);        // [4]

    if (blockIdx.x < 256) {
        float cs0 = 0.f, cs1 = 0.f, cs2 = 0.f, cs3 = 0.f, sS = 0.f;

        #pragma unroll
        for (int it = 0; it < 4; it++) {
            int row = blockIdx.x * 32 + it * 8 + wid;
            const float* p = (row < NHALF) ? (src + (size_t)row * DDIM)
                                           : (tgt + (size_t)(row - NHALF) * DDIM);
            float4 v = ((const float4*)p)[lane];

            cs0 += v.x; cs1 += v.y; cs2 += v.z; cs3 += v.w;

            float sq = v.x * v.x + v.y * v.y + v.z * v.z + v.w * v.w;
            #pragma unroll
            for (int o = 16; o; o >>= 1) sq += __shfl_xor_sync(0xffffffffu, sq, o);
            if (lane == 0) { g_rowsq[row] = sq; sS += sq; }

            __nv_bfloat16 h0 = __float2bfloat16_rn(v.x);
            __nv_bfloat16 h1 = __float2bfloat16_rn(v.y);
            __nv_bfloat16 h2 = __float2bfloat16_rn(v.z);
            __nv_bfloat16 h3 = __float2bfloat16_rn(v.w);
            __nv_bfloat16 l0 = __float2bfloat16_rn(v.x - __bfloat162float(h0));
            __nv_bfloat16 l1 = __float2bfloat16_rn(v.y - __bfloat162float(h1));
            __nv_bfloat16 l2 = __float2bfloat16_rn(v.z - __bfloat162float(h2));
            __nv_bfloat16 l3 = __float2bfloat16_rn(v.w - __bfloat162float(h3));

            uint2 ph, pl;
            ph.x = (uint32_t)__bfloat16_as_ushort(h0) | ((uint32_t)__bfloat16_as_ushort(h1) << 16);
            ph.y = (uint32_t)__bfloat16_as_ushort(h2) | ((uint32_t)__bfloat16_as_ushort(h3) << 16);
            pl.x = (uint32_t)__bfloat16_as_ushort(l0) | ((uint32_t)__bfloat16_as_ushort(l1) << 16);
            pl.y = (uint32_t)__bfloat16_as_ushort(l2) | ((uint32_t)__bfloat16_as_ushort(l3) << 16);
            *(uint2*)&g_hi[(size_t)row * DDIM + lane * 4] = ph;
            *(uint2*)&g_lo[(size_t)row * DDIM + lane * 4] = pl;
        }

        *(float4*)&shc[wid * DDIM + lane * 4] = make_float4(cs0, cs1, cs2, cs3);
        if (lane == 0) shs[wid] = sS;
        __syncthreads();

        if (tid < DDIM) {
            float s = 0.f;
            #pragma unroll
            for (int w = 0; w < 8; w++) s += shc[w * DDIM + tid];
            atomicAdd(&g_colsum[tid], (double)s);
        }
        if (tid == 0) {
            float s = 0.f;
            #pragma unroll
            for (int w = 0; w < 8; w++) s += shs[w];
            atomicAdd(&g_S, (double)s);
        }
        __threadfence();   // make rowsq / hi / lo / colsum visible device-wide
    }
    __syncthreads();

    // ---- barrier arrival; last arriver computes scale and releases ----
    if (tid == 0) {
        unsigned tk = atomicInc(&g_done_prep, NCTA - 1);   // wraps to 0
        sflag = (tk == NCTA - 1) ? 1u : 0u;
    }
    __syncthreads();

    if (sflag) {
        // last CTA: parallel reduce of sum(colsum^2), then release
        double p = 0.0;
        if (tid < DDIM) { double c = g_colsum[tid]; p = c * c; }
        #pragma unroll
        for (int o = 16; o; o >>= 1) p += __shfl_xor_sync(0xffffffffu, p, o);
        if (lane == 0 && tid < DDIM) sred[tid >> 5] = p;
        __syncthreads();
        if (tid == 0) {
            double T2 = sred[0] + sred[1] + sred[2] + sred[3];
            double M = (double)NROWS;
            double bw = (2.0 * M * g_S - 2.0 * T2) / (M * M - M);
            bw = bw / 4.0;                     // KERNEL_MUL^(KERNEL_NUM//2)
            g_c = (float)(1.0 / (16.0 * bw));  // widest kernel coefficient
            g_acc = 0.0;
            __threadfence();
            atomicExch(&g_go, 1u);             // release
        }
        __syncthreads();
    } else {
        if (tid == 0) {
            while (atomicAdd(&g_go, 0u) == 0u) __nanosleep(64);
        }
        __syncthreads();
    }
    __threadfence();   // acquire: see all prep writes

    // ================= GEMM PHASE =================
    int R = (wid & 3) * 32;
    int C = (wid >> 2) * 32;
    int mat = lane >> 3;
    int rin = lane & 7;
    int mrow = (mat & 1) * 8 + rin;
    int csel = mat >> 1;

    uint32_t rowAoff[2], nrowoff[2];
    #pragma unroll
    for (int mt = 0; mt < 2; mt++) rowAoff[mt] = (uint32_t)((R + mt * 16 + mrow) * 256);
    #pragma unroll
    for (int np = 0; np < 2; np++) nrowoff[np] = (uint32_t)((C + np * 16 + mrow) * 128);

    float cfac = g_c;
    float nc2 = -cfac * L2E;
    u64t nc22 = pk(nc2, nc2);
    float c2s = 2.0f * cfac * L2E;
    u64t c22 = pk(c2s, c2s);

    int b = blockIdx.x;
    int t = b * 14 + (b < 16 ? b : 16);
    int tend = t + 14 + (b < 16 ? 1 : 0);

    int pair = t >> 1, half = t & 1;
    int bi = 0, rem = pair;
    while (rem >= NB - bi) { rem -= NB - bi; bi++; }
    int bj = bi + rem;

    float total = 0.0f;

    while (t < tend) {
        int rA0 = bi * 128;
        stageA(sb, rA0, tid);
        stageB(sb + B_BASE, bj * 128 + half * 64, 0, tid);
        cp_commit();
        stageB(sb + B_BASE + B_STRIDE, bj * 128 + half * 64, 1, tid);
        cp_commit();
        int p = 0;

        bool runend = false;
        while (!runend) {
            int rB0 = bj * 128 + half * 64;
            float w = ((bi < NB / 2) == (bj < NB / 2)) ? 1.0f : -1.0f;
            if (bi != bj) w *= 2.0f;

            int halfn = half ^ 1;
            int bjn = bj + (half & 1);
            bool next_in_run = (t + 1 < tend) && !((half == 1) && (bj == NB - 1));
            int rB0n = bjn * 128 + halfn * 64;

            float acc[2][4][4];
            #pragma unroll
            for (int mt = 0; mt < 2; mt++)
                #pragma unroll
                for (int nt = 0; nt < 4; nt++)
                    #pragma unroll
                    for (int r = 0; r < 4; r++) acc[mt][nt][r] = 0.0f;

            #pragma unroll
            for (int kh = 0; kh < 2; kh++) {
                if (kh == 0 || next_in_run) cp_wait<1>();
                else cp_wait<0>();
                __syncthreads();
                if (next_in_run) {
                    stageB(sb + B_BASE + ((p + 2) % 3) * B_STRIDE, rB0n, kh, tid);
                    cp_commit();
                }
                uint32_t bb = sb + B_BASE + p * B_STRIDE;

                #pragma unroll
                for (int ks = 0; ks < 4; ks++) {
                    int cB = ks * 2 + csel;
                    uint32_t swz = (uint32_t)(((cB ^ rin) & 7) * 16);
                    uint32_t aoff = (uint32_t)(kh * 128) + swz;

                    uint32_t ah[2][4], al[2][4], bh[4][2], bl[4][2];
                    #pragma unroll
                    for (int mt = 0; mt < 2; mt++) {
                        LDSM_X4(ah[mt][0], ah[mt][1], ah[mt][2], ah[mt][3],
                                sb + A_HI_OFF + rowAoff[mt] + aoff);
                        LDSM_X4(al[mt][0], al[mt][1], al[mt][2], al[mt][3],
                                sb + A_LO_OFF + rowAoff[mt] + aoff);
                    }
                    #pragma unroll
                    for (int np = 0; np < 2; np++) {
                        uint32_t r0, r1, r2, r3;
                        LDSM_X4(r0, r1, r2, r3, bb + nrowoff[np] + swz);
                        bh[np * 2 + 0][0] = r0; bh[np * 2 + 0][1] = r2;
                        bh[np * 2 + 1][0] = r1; bh[np * 2 + 1][1] = r3;
                        LDSM_X4(r0, r1, r2, r3, bb + 8192 + nrowoff[np] + swz);
                        bl[np * 2 + 0][0] = r0; bl[np * 2 + 0][1] = r2;
                        bl[np * 2 + 1][0] = r1; bl[np * 2 + 1][1] = r3;
                    }
                    #pragma unroll
                    for (int mt = 0; mt < 2; mt++) {
                        #pragma unroll
                        for (int nt = 0; nt < 4; nt++) {
                            MMA_BF16(acc[mt][nt], ah[mt], bh[nt]);
                            MMA_BF16(acc[mt][nt], ah[mt], bl[nt]);
                            MMA_BF16(acc[mt][nt], al[mt], bh[nt]);
                        }
                    }
                }
                p = (p + 1) % 3;
            }

            // ---- fused RBF epilogue ----
            u64t kA2[2][2];
            #pragma unroll
            for (int mt = 0; mt < 2; mt++)
                #pragma unroll
                for (int h = 0; h < 2; h++) {
                    float kv = nc2 * g_rowsq[rA0 + R + mt * 16 + h * 8 + (lane >> 2)];
                    kA2[mt][h] = pk(kv, kv);
                }
            u64t acc2 = pk(0.0f, 0.0f);
            #pragma unroll
            for (int nt = 0; nt < 4; nt++) {
                float2 qraw = *(const float2*)&g_rowsq[rB0 + C + nt * 8 + 2 * (lane & 3)];
                u64t base2 = pk_mul(pk(qraw.x, qraw.y), nc22);
                #pragma unroll
                for (int mt = 0; mt < 2; mt++) {
                    #pragma unroll
                    for (int h = 0; h < 2; h++) {
                        u64t d2 = pk(acc[mt][nt][h * 2], acc[mt][nt][h * 2 + 1]);
                        u64t arg = pk_fma(d2, c22, pk_add(base2, kA2[mt][h]));
                        float ax, bx; unpk(ax, bx, arg);
                        u64t a1 = pk(ex2f(ax), ex2f(bx));
                        u64t a2 = pk_mul(a1, a1);
                        u64t a4 = pk_mul(a2, a2);
                        u64t a8 = pk_mul(a4, a4);
                        u64t u  = pk_fma(a8, a8, a8);   // a8 + a16
                        u64t s  = pk_add(pk_add(u, a4), pk_add(a2, a1));
                        acc2 = pk_add(acc2, s);
                    }
                }
            }
            float plo, phi; unpk(plo, phi, acc2);
            total += w * (plo + phi);

            t++;
            if (next_in_run) {
                bj = bjn; half = halfn;
            } else {
                if (t < tend) { bi++; bj = bi; half = 0; }
                runend = true;
            }
        }
    }

    // ---- final reduction + self-resetting completion ticket ----
    #pragma unroll
    for (int o = 16; o; o >>= 1) total += __shfl_xor_sync(0xffffffffu, total, o);
    if (lane == 0) {
        atomicAdd(&g_acc, (double)total);
        __threadfence();
    }
    __syncthreads();
    if (tid == 0) {
        unsigned tk = atomicInc(&g_done_main, NCTA - 1);   // wraps to 0
        sflag = (tk == NCTA - 1) ? 1u : 0u;
    }
    __syncthreads();
    if (sflag) {
        __threadfence();
        if (tid == 0) {
            out[0] = (float)(g_acc / ((double)NHALF * (double)NHALF));
            g_S = 0.0;                        // clean state for next replay
            atomicExch(&g_go, 0u);            // re-arm barrier
        }
        if (tid < DDIM) g_colsum[tid] = 0.0;
    }
}

extern "C" void kernel_launch(void* const* d_in, const int* in_sizes, int n_in,
                              void* d_out, int out_size) {
    const float* src = (const float*)d_in[0];
    const float* tgt = (const float*)d_in[1];
    float* out = (float*)d_out;

    cudaFuncSetAttribute(k_fused, cudaFuncAttributeMaxDynamicSharedMemorySize, SMEM_DYN);

    k_fused<<<NCTA, 256, SMEM_DYN>>>(src, tgt, out);
}

// round 14
// speedup vs baseline: 1.8039x; 1.0179x over previous
#include <cuda_runtime.h>
#include <cuda_bf16.h>
#include <cstdint>

// MMD loss, single fused persistent kernel: prep (rowsq + bf16 hi/lo split +
// closed-form bandwidth) -> device-wide spin barrier (all 296 CTAs resident)
// -> run-ordered bf16 3-term split Gram (mma.sync, term-outer issue order for
// 8-deep accumulator independence) with A-block reuse, 3-deep cp.async B
// pipeline, XOR-swizzled smem, fused single-exp 5-kernel RBF mixture epilogue.

#define NROWS 8192
#define NHALF 4096
#define DDIM  128
#define NB    64
#define NTILES 4160
#define NCTA  296
#define L2E   1.4426950408889634f

#define A_HI_OFF 0
#define A_LO_OFF 32768
#define B_BASE   65536
#define B_STRIDE 16384
#define SMEM_DYN (B_BASE + 3 * B_STRIDE)   // 114688

__device__ double g_S = 0.0;
__device__ double g_colsum[DDIM];
__device__ float  g_rowsq[NROWS];
__device__ double g_acc;
__device__ float  g_c;
__device__ unsigned g_done_prep = 0u;
__device__ unsigned g_done_main = 0u;
__device__ unsigned g_go = 0u;
__device__ __align__(16) __nv_bfloat16 g_hi[NROWS * DDIM];
__device__ __align__(16) __nv_bfloat16 g_lo[NROWS * DDIM];

// ================= helpers =================
__device__ __forceinline__ uint32_t smem_u32(const void* p) {
    uint32_t a;
    asm("{ .reg .u64 t; cvta.to.shared.u64 t, %1; cvt.u32.u64 %0, t; }" : "=r"(a) : "l"(p));
    return a;
}
__device__ __forceinline__ float ex2f(float x) {
    float r; asm("ex2.approx.ftz.f32 %0, %1;" : "=f"(r) : "f"(x));
    return r;
}
__device__ __forceinline__ void cp_async16(uint32_t dst, const void* src) {
    asm volatile("cp.async.cg.shared.global [%0], [%1], 16;" :: "r"(dst), "l"(src) : "memory");
}
__device__ __forceinline__ void cp_commit() {
    asm volatile("cp.async.commit_group;" ::: "memory");
}
template <int N>
__device__ __forceinline__ void cp_wait() {
    asm volatile("cp.async.wait_group %0;" :: "n"(N) : "memory");
}

#define LDSM_X4(r0, r1, r2, r3, addr) \
    asm volatile("ldmatrix.sync.aligned.m8n8.x4.shared.b16 {%0,%1,%2,%3}, [%4];" \
        : "=r"(r0), "=r"(r1), "=r"(r2), "=r"(r3) : "r"(addr))

#define MMA_BF16(d, a, b) \
    asm volatile("mma.sync.aligned.m16n8k16.row.col.f32.bf16.bf16.f32 " \
        "{%0,%1,%2,%3}, {%4,%5,%6,%7}, {%8,%9}, {%0,%1,%2,%3};" \
        : "+f"((d)[0]), "+f"((d)[1]), "+f"((d)[2]), "+f"((d)[3]) \
        : "r"((a)[0]), "r"((a)[1]), "r"((a)[2]), "r"((a)[3]), "r"((b)[0]), "r"((b)[1]))

typedef unsigned long long u64t;
__device__ __forceinline__ u64t pk(float a, float b) {
    u64t r; asm("mov.b64 %0, {%1, %2};" : "=l"(r) : "f"(a), "f"(b)); return r;
}
__device__ __forceinline__ void unpk(float& a, float& b, u64t v) {
    asm("mov.b64 {%0, %1}, %2;" : "=f"(a), "=f"(b) : "l"(v));
}
__device__ __forceinline__ u64t pk_fma(u64t a, u64t b, u64t c) {
    u64t r; asm("fma.rn.f32x2 %0, %1, %2, %3;" : "=l"(r) : "l"(a), "l"(b), "l"(c)); return r;
}
__device__ __forceinline__ u64t pk_mul(u64t a, u64t b) {
    u64t r; asm("mul.rn.f32x2 %0, %1, %2;" : "=l"(r) : "l"(a), "l"(b)); return r;
}
__device__ __forceinline__ u64t pk_add(u64t a, u64t b) {
    u64t r; asm("add.rn.f32x2 %0, %1, %2;" : "=l"(r) : "l"(a), "l"(b)); return r;
}

// ================= staging =================
__device__ __forceinline__ void stageA(uint32_t sb, int rA0, int tid) {
    #pragma unroll
    for (int i = 0; i < 16; i++) {
        int idx = tid + i * 256;
        int plane = idx >> 11;
        int q = idx & 2047;
        int r = q >> 4, c = q & 15;
        uint32_t dst = sb + (plane ? A_LO_OFF : A_HI_OFF)
                     + (uint32_t)(r * 256 + (((c & 8) | ((c ^ r) & 7)) * 16));
        const __nv_bfloat16* s = (plane ? g_lo : g_hi) + (size_t)(rA0 + r) * DDIM + c * 8;
        cp_async16(dst, s);
    }
}

__device__ __forceinline__ void stageB(uint32_t bb, int rB0, int kh, int tid) {
    #pragma unroll
    for (int i = 0; i < 4; i++) {
        int idx = tid + i * 256;
        int plane = idx >> 9;
        int q = idx & 511;
        int r = q >> 3, c = q & 7;
        uint32_t dst = bb + (plane ? 8192 : 0)
                     + (uint32_t)(r * 128 + (((c ^ r) & 7) * 16));
        const __nv_bfloat16* s = (plane ? g_lo : g_hi)
            + (size_t)(rB0 + r) * DDIM + kh * 64 + c * 8;
        cp_async16(dst, s);
    }
}

// ================= fused kernel =================
__global__ void __launch_bounds__(256, 2)
k_fused(const float* __restrict__ src, const float* __restrict__ tgt,
        float* __restrict__ out) {
    extern __shared__ __align__(16) char dsm[];
    __shared__ unsigned sflag;
    uint32_t sb = smem_u32(dsm);

    int tid = threadIdx.x;
    int wid = tid >> 5, lane = tid & 31;

    // ================= PREP PHASE =================
    float* shc = (float*)dsm;                    // [8][128]
    float* shs = (float*)(dsm + 4096);           // [8]
    double* sred = (double*)(dsm + 4224);        // [4]

    if (blockIdx.x < 256) {
        float cs0 = 0.f, cs1 = 0.f, cs2 = 0.f, cs3 = 0.f, sS = 0.f;

        #pragma unroll
        for (int it = 0; it < 4; it++) {
            int row = blockIdx.x * 32 + it * 8 + wid;
            const float* p = (row < NHALF) ? (src + (size_t)row * DDIM)
                                           : (tgt + (size_t)(row - NHALF) * DDIM);
            float4 v = ((const float4*)p)[lane];

            cs0 += v.x; cs1 += v.y; cs2 += v.z; cs3 += v.w;

            float sq = v.x * v.x + v.y * v.y + v.z * v.z + v.w * v.w;
            #pragma unroll
            for (int o = 16; o; o >>= 1) sq += __shfl_xor_sync(0xffffffffu, sq, o);
            if (lane == 0) { g_rowsq[row] = sq; sS += sq; }

            __nv_bfloat16 h0 = __float2bfloat16_rn(v.x);
            __nv_bfloat16 h1 = __float2bfloat16_rn(v.y);
            __nv_bfloat16 h2 = __float2bfloat16_rn(v.z);
            __nv_bfloat16 h3 = __float2bfloat16_rn(v.w);
            __nv_bfloat16 l0 = __float2bfloat16_rn(v.x - __bfloat162float(h0));
            __nv_bfloat16 l1 = __float2bfloat16_rn(v.y - __bfloat162float(h1));
            __nv_bfloat16 l2 = __float2bfloat16_rn(v.z - __bfloat162float(h2));
            __nv_bfloat16 l3 = __float2bfloat16_rn(v.w - __bfloat162float(h3));

            uint2 ph, pl;
            ph.x = (uint32_t)__bfloat16_as_ushort(h0) | ((uint32_t)__bfloat16_as_ushort(h1) << 16);
            ph.y = (uint32_t)__bfloat16_as_ushort(h2) | ((uint32_t)__bfloat16_as_ushort(h3) << 16);
            pl.x = (uint32_t)__bfloat16_as_ushort(l0) | ((uint32_t)__bfloat16_as_ushort(l1) << 16);
            pl.y = (uint32_t)__bfloat16_as_ushort(l2) | ((uint32_t)__bfloat16_as_ushort(l3) << 16);
            *(uint2*)&g_hi[(size_t)row * DDIM + lane * 4] = ph;
            *(uint2*)&g_lo[(size_t)row * DDIM + lane * 4] = pl;
        }

        *(float4*)&shc[wid * DDIM + lane * 4] = make_float4(cs0, cs1, cs2, cs3);
        if (lane == 0) shs[wid] = sS;
        __syncthreads();

        if (tid < DDIM) {
            float s = 0.f;
            #pragma unroll
            for (int w = 0; w < 8; w++) s += shc[w * DDIM + tid];
            atomicAdd(&g_colsum[tid], (double)s);
        }
        if (tid == 0) {
            float s = 0.f;
            #pragma unroll
            for (int w = 0; w < 8; w++) s += shs[w];
            atomicAdd(&g_S, (double)s);
        }
        __threadfence();
    }
    __syncthreads();

    // ---- barrier arrival; last arriver computes scale and releases ----
    if (tid == 0) {
        unsigned tk = atomicInc(&g_done_prep, NCTA - 1);
        sflag = (tk == NCTA - 1) ? 1u : 0u;
    }
    __syncthreads();

    if (sflag) {
        double p = 0.0;
        if (tid < DDIM) { double c = g_colsum[tid]; p = c * c; }
        #pragma unroll
        for (int o = 16; o; o >>= 1) p += __shfl_xor_sync(0xffffffffu, p, o);
        if (lane == 0 && tid < DDIM) sred[tid >> 5] = p;
        __syncthreads();
        if (tid == 0) {
            double T2 = sred[0] + sred[1] + sred[2] + sred[3];
            double M = (double)NROWS;
            double bw = (2.0 * M * g_S - 2.0 * T2) / (M * M - M);
            bw = bw / 4.0;                     // KERNEL_MUL^(KERNEL_NUM//2)
            g_c = (float)(1.0 / (16.0 * bw));  // widest kernel coefficient
            g_acc = 0.0;
            __threadfence();
            atomicExch(&g_go, 1u);
        }
        __syncthreads();
    } else {
        if (tid == 0) {
            while (atomicAdd(&g_go, 0u) == 0u) __nanosleep(64);
        }
        __syncthreads();
    }
    __threadfence();

    // ================= GEMM PHASE =================
    int R = (wid & 3) * 32;
    int C = (wid >> 2) * 32;
    int mat = lane >> 3;
    int rin = lane & 7;
    int mrow = (mat & 1) * 8 + rin;
    int csel = mat >> 1;

    uint32_t rowAoff[2], nrowoff[2];
    #pragma unroll
    for (int mt = 0; mt < 2; mt++) rowAoff[mt] = (uint32_t)((R + mt * 16 + mrow) * 256);
    #pragma unroll
    for (int np = 0; np < 2; np++) nrowoff[np] = (uint32_t)((C + np * 16 + mrow) * 128);

    float cfac = g_c;
    float nc2 = -cfac * L2E;
    u64t nc22 = pk(nc2, nc2);
    float c2s = 2.0f * cfac * L2E;
    u64t c22 = pk(c2s, c2s);

    int b = blockIdx.x;
    int t = b * 14 + (b < 16 ? b : 16);
    int tend = t + 14 + (b < 16 ? 1 : 0);

    int pair = t >> 1, half = t & 1;
    int bi = 0, rem = pair;
    while (rem >= NB - bi) { rem -= NB - bi; bi++; }
    int bj = bi + rem;

    float total = 0.0f;

    while (t < tend) {
        int rA0 = bi * 128;
        stageA(sb, rA0, tid);
        stageB(sb + B_BASE, bj * 128 + half * 64, 0, tid);
        cp_commit();
        stageB(sb + B_BASE + B_STRIDE, bj * 128 + half * 64, 1, tid);
        cp_commit();
        int p = 0;

        bool runend = false;
        while (!runend) {
            int rB0 = bj * 128 + half * 64;
            float w = ((bi < NB / 2) == (bj < NB / 2)) ? 1.0f : -1.0f;
            if (bi != bj) w *= 2.0f;

            int halfn = half ^ 1;
            int bjn = bj + (half & 1);
            bool next_in_run = (t + 1 < tend) && !((half == 1) && (bj == NB - 1));
            int rB0n = bjn * 128 + halfn * 64;

            float acc[2][4][4];
            #pragma unroll
            for (int mt = 0; mt < 2; mt++)
                #pragma unroll
                for (int nt = 0; nt < 4; nt++)
                    #pragma unroll
                    for (int r = 0; r < 4; r++) acc[mt][nt][r] = 0.0f;

            #pragma unroll
            for (int kh = 0; kh < 2; kh++) {
                if (kh == 0 || next_in_run) cp_wait<1>();
                else cp_wait<0>();
                __syncthreads();
                if (next_in_run) {
                    stageB(sb + B_BASE + ((p + 2) % 3) * B_STRIDE, rB0n, kh, tid);
                    cp_commit();
                }
                uint32_t bb = sb + B_BASE + p * B_STRIDE;

                #pragma unroll
                for (int ks = 0; ks < 4; ks++) {
                    int cB = ks * 2 + csel;
                    uint32_t swz = (uint32_t)(((cB ^ rin) & 7) * 16);
                    uint32_t aoff = (uint32_t)(kh * 128) + swz;

                    uint32_t ah[2][4], al[2][4], bh[4][2], bl[4][2];
                    #pragma unroll
                    for (int mt = 0; mt < 2; mt++) {
                        LDSM_X4(ah[mt][0], ah[mt][1], ah[mt][2], ah[mt][3],
                                sb + A_HI_OFF + rowAoff[mt] + aoff);
                        LDSM_X4(al[mt][0], al[mt][1], al[mt][2], al[mt][3],
                                sb + A_LO_OFF + rowAoff[mt] + aoff);
                    }
                    #pragma unroll
                    for (int np = 0; np < 2; np++) {
                        uint32_t r0, r1, r2, r3;
                        LDSM_X4(r0, r1, r2, r3, bb + nrowoff[np] + swz);
                        bh[np * 2 + 0][0] = r0; bh[np * 2 + 0][1] = r2;
                        bh[np * 2 + 1][0] = r1; bh[np * 2 + 1][1] = r3;
                        LDSM_X4(r0, r1, r2, r3, bb + 8192 + nrowoff[np] + swz);
                        bl[np * 2 + 0][0] = r0; bl[np * 2 + 0][1] = r2;
                        bl[np * 2 + 1][0] = r1; bl[np * 2 + 1][1] = r3;
                    }
                    // term-outer issue order: 8 independent accumulators
                    // between any two MMAs that reuse the same acc.
                    #pragma unroll
                    for (int mt = 0; mt < 2; mt++)
                        #pragma unroll
                        for (int nt = 0; nt < 4; nt++)
                            MMA_BF16(acc[mt][nt], ah[mt], bh[nt]);
                    #pragma unroll
                    for (int mt = 0; mt < 2; mt++)
                        #pragma unroll
                        for (int nt = 0; nt < 4; nt++)
                            MMA_BF16(acc[mt][nt], ah[mt], bl[nt]);
                    #pragma unroll
                    for (int mt = 0; mt < 2; mt++)
                        #pragma unroll
                        for (int nt = 0; nt < 4; nt++)
                            MMA_BF16(acc[mt][nt], al[mt], bh[nt]);
                }
                p = (p + 1) % 3;
            }

            // ---- fused RBF epilogue ----
            u64t kA2[2][2];
            #pragma unroll
            for (int mt = 0; mt < 2; mt++)
                #pragma unroll
                for (int h = 0; h < 2; h++) {
                    float kv = nc2 * g_rowsq[rA0 + R + mt * 16 + h * 8 + (lane >> 2)];
                    kA2[mt][h] = pk(kv, kv);
                }
            u64t acc2 = pk(0.0f, 0.0f);
            #pragma unroll
            for (int nt = 0; nt < 4; nt++) {
                float2 qraw = *(const float2*)&g_rowsq[rB0 + C + nt * 8 + 2 * (lane & 3)];
                u64t base2 = pk_mul(pk(qraw.x, qraw.y), nc22);
                #pragma unroll
                for (int mt = 0; mt < 2; mt++) {
                    #pragma unroll
                    for (int h = 0; h < 2; h++) {
                        u64t d2 = pk(acc[mt][nt][h * 2], acc[mt][nt][h * 2 + 1]);
                        u64t arg = pk_fma(d2, c22, pk_add(base2, kA2[mt][h]));
                        float ax, bx; unpk(ax, bx, arg);
                        u64t a1 = pk(ex2f(ax), ex2f(bx));
                        u64t a2 = pk_mul(a1, a1);
                        u64t a4 = pk_mul(a2, a2);
                        u64t a8 = pk_mul(a4, a4);
                        u64t u  = pk_fma(a8, a8, a8);   // a8 + a16
                        u64t s  = pk_add(pk_add(u, a4), pk_add(a2, a1));
                        acc2 = pk_add(acc2, s);
                    }
                }
            }
            float plo, phi; unpk(plo, phi, acc2);
            total += w * (plo + phi);

            t++;
            if (next_in_run) {
                bj = bjn; half = halfn;
            } else {
                if (t < tend) { bi++; bj = bi; half = 0; }
                runend = true;
            }
        }
    }

    // ---- final reduction + self-resetting completion ticket ----
    #pragma unroll
    for (int o = 16; o; o >>= 1) total += __shfl_xor_sync(0xffffffffu, total, o);
    if (lane == 0) {
        atomicAdd(&g_acc, (double)total);
        __threadfence();
    }
    __syncthreads();
    if (tid == 0) {
        unsigned tk = atomicInc(&g_done_main, NCTA - 1);
        sflag = (tk == NCTA - 1) ? 1u : 0u;
    }
    __syncthreads();
    if (sflag) {
        __threadfence();
        if (tid == 0) {
            out[0] = (float)(g_acc / ((double)NHALF * (double)NHALF));
            g_S = 0.0;
            atomicExch(&g_go, 0u);
        }
        if (tid < DDIM) g_colsum[tid] = 0.0;
    }
}

extern "C" void kernel_launch(void* const* d_in, const int* in_sizes, int n_in,
                              void* d_out, int out_size) {
    const float* src = (const float*)d_in[0];
    const float* tgt = (const float*)d_in[1];
    float* out = (float*)d_out;

    cudaFuncSetAttribute(k_fused, cudaFuncAttributeMaxDynamicSharedMemorySize, SMEM_DYN);

    k_fused<<<NCTA, 256, SMEM_DYN>>>(src, tgt, out);
}